// round 13
// baseline (speedup 1.0000x reference)
#include <cuda_runtime.h>
#include <cuda_bf16.h>
#include <math.h>

// Problem constants
#define BB 2
#define TT 2048
#define CC 1024
#define HH 16
#define HD 64
#define MM (BB*TT)        // 4096
#define NQKV (3*CC)       // 3072

// Scratch (device globals — allocation-free)
__device__ float g_q[(size_t)BB*HH*TT*HD];
__device__ float g_k[(size_t)BB*HH*TT*HD];
__device__ float g_v[(size_t)BB*HH*TT*HD];
// bf16 hi/lo planes for GEMM inputs
__device__ __nv_bfloat16 g_xh[(size_t)MM*CC],   g_xl[(size_t)MM*CC];
__device__ __nv_bfloat16 g_wah[(size_t)NQKV*CC], g_wal[(size_t)NQKV*CC];
__device__ __nv_bfloat16 g_wph[(size_t)CC*CC],  g_wpl[(size_t)CC*CC];
__device__ __nv_bfloat16 g_yh[(size_t)MM*CC],   g_yl[(size_t)MM*CC];

// ---------------------------------------------------------------------------
// Helpers
// ---------------------------------------------------------------------------
__device__ __forceinline__ unsigned bfhi2(float x, float y) {
    __nv_bfloat162 p = __floats2bfloat162_rn(x, y);
    return *(unsigned*)&p;
}
__device__ __forceinline__ unsigned bflo2(float x, float y) {
    float hx = __bfloat162float(__float2bfloat16_rn(x));
    float hy = __bfloat162float(__float2bfloat16_rn(y));
    return bfhi2(x - hx, y - hy);
}
__device__ __forceinline__ void split4bf(float4 v, uint2& h, uint2& l) {
    h.x = bfhi2(v.x, v.y); h.y = bfhi2(v.z, v.w);
    l.x = bflo2(v.x, v.y); l.y = bflo2(v.z, v.w);
}
__device__ __forceinline__ unsigned smem_u32(const void* p) {
    return (unsigned)__cvta_generic_to_shared(p);
}
__device__ __forceinline__ void mma_bf16(float d[4], const unsigned a[4],
                                         unsigned b0, unsigned b1) {
    asm volatile(
        "mma.sync.aligned.m16n8k16.row.col.f32.bf16.bf16.f32 "
        "{%0,%1,%2,%3}, {%4,%5,%6,%7}, {%8,%9}, {%0,%1,%2,%3};"
        : "+f"(d[0]), "+f"(d[1]), "+f"(d[2]), "+f"(d[3])
        : "r"(a[0]), "r"(a[1]), "r"(a[2]), "r"(a[3]), "r"(b0), "r"(b1));
}
__device__ __forceinline__ void ldmx4(unsigned r[4], const void* p) {
    unsigned addr = smem_u32(p);
    asm volatile("ldmatrix.sync.aligned.m8n8.x4.shared.b16 {%0,%1,%2,%3}, [%4];"
                 : "=r"(r[0]), "=r"(r[1]), "=r"(r[2]), "=r"(r[3]) : "r"(addr));
}
__device__ __forceinline__ void ldmx2t(unsigned& r0, unsigned& r1, const void* p) {
    unsigned addr = smem_u32(p);
    asm volatile("ldmatrix.sync.aligned.m8n8.x2.trans.shared.b16 {%0,%1}, [%2];"
                 : "=r"(r0), "=r"(r1) : "r"(addr));
}
__device__ __forceinline__ void cp_async16(unsigned dst, const void* src) {
    asm volatile("cp.async.cg.shared.global [%0], [%1], 16;"
                 :: "r"(dst), "l"(src) : "memory");
}
__device__ __forceinline__ void cp_commit() {
    asm volatile("cp.async.commit_group;" ::: "memory");
}

// ---------------------------------------------------------------------------
// Convert: fp32 -> bf16 hi/lo planes
// ---------------------------------------------------------------------------
__global__ void cvt_hilo(const float4* __restrict__ src, uint2* __restrict__ dh,
                         uint2* __restrict__ dl, int n4) {
    int i = blockIdx.x * blockDim.x + threadIdx.x;
    if (i < n4) {
        uint2 h, l;
        split4bf(src[i], h, l);
        dh[i] = h;
        dl[i] = l;
    }
}

// ---------------------------------------------------------------------------
// Pipelined bf16x3 GEMM: out[m,n] = sum_k A[m,k]*W[n,k] + bias[n]
// 64x128 tile, BK=32, 3-stage cp.async (2-deep prefetch, ONE sync/iter),
// 256 threads = 8 warps (2x4), 32x32 per warp. smem 92160B/CTA -> 2 CTAs/SM.
// ---------------------------------------------------------------------------
template<bool QKV_SCATTER>
__global__ __launch_bounds__(256, 2)
void gemm_cp(const __nv_bfloat16* __restrict__ Agh, const __nv_bfloat16* __restrict__ Agl,
             const __nv_bfloat16* __restrict__ Wgh, const __nv_bfloat16* __restrict__ Wgl,
             const float* __restrict__ bias, float* __restrict__ Cout,
             int K, int N) {
    constexpr int BK = 32, LD = 40;
    constexpr int APLANE = 64 * LD;           // 2560 bf16 units
    constexpr int WPLANE = 128 * LD;          // 5120
    constexpr int STAGE = 2 * APLANE + 2 * WPLANE;   // 15360 units = 30720 B
    extern __shared__ __nv_bfloat16 sm[];     // 3 * STAGE

    const int tid = threadIdx.x;
    const int lane = tid & 31, w = tid >> 5;
    const int g = lane >> 2, t = lane & 3;
    const int m0 = blockIdx.y * 64, n0 = blockIdx.x * 128;
    const int wm = (w >> 2) * 32, wn = (w & 3) * 32;

    const int arow = lane & 15, acol8 = (lane >> 4) << 3;
    const int brow = (lane & 7) + ((lane >> 4) << 3), bcol8 = lane & 8;

#define ISSUE_STAGE(sidx, kt)                                                  \
    do {                                                                       \
        __nv_bfloat16* sb = sm + (sidx) * STAGE;                               \
        {   /* A planes: 256 chunks each (1 per thread) */                     \
            int row = tid >> 2, c4 = tid & 3;                                  \
            cp_async16(smem_u32(sb + row * LD + c4 * 8),                       \
                       Agh + (size_t)(m0 + row) * K + (kt) + c4 * 8);          \
            cp_async16(smem_u32(sb + APLANE + row * LD + c4 * 8),              \
                       Agl + (size_t)(m0 + row) * K + (kt) + c4 * 8);          \
        }                                                                      \
        _Pragma("unroll")                                                      \
        for (int rep = 0; rep < 2; rep++) {  /* W planes: 512 chunks each */   \
            int c = tid + rep * 256;                                           \
            int row = c >> 2, c4 = c & 3;                                      \
            cp_async16(smem_u32(sb + 2 * APLANE + row * LD + c4 * 8),          \
                       Wgh + (size_t)(n0 + row) * K + (kt) + c4 * 8);          \
            cp_async16(smem_u32(sb + 2 * APLANE + WPLANE + row * LD + c4 * 8), \
                       Wgl + (size_t)(n0 + row) * K + (kt) + c4 * 8);          \
        }                                                                      \
        cp_commit();                                                           \
    } while (0)

    float acc[2][4][4] = {};

    const int niter = K / BK;                 // 32
    ISSUE_STAGE(0, 0);
    ISSUE_STAGE(1, BK);

    for (int it = 0; it < niter; it++) {
        if (it + 1 < niter)
            asm volatile("cp.async.wait_group 1;" ::: "memory");
        else
            asm volatile("cp.async.wait_group 0;" ::: "memory");
        __syncthreads();
        // prefetch 2 ahead into the buffer freed by iteration it-1
        if (it + 2 < niter) ISSUE_STAGE((it + 2) % 3, (it + 2) * BK);

        const __nv_bfloat16* Ah = sm + (it % 3) * STAGE;
        const __nv_bfloat16* Al = Ah + APLANE;
        const __nv_bfloat16* Wh = Al + APLANE;
        const __nv_bfloat16* Wl = Wh + WPLANE;

#pragma unroll
        for (int s = 0; s < 2; s++) {         // two k16 slices
            const int kc0 = s * 16;
            unsigned ah[2][4], al[2][4];
            ldmx4(ah[0], &Ah[(wm + arow) * LD + kc0 + acol8]);
            ldmx4(ah[1], &Ah[(wm + 16 + arow) * LD + kc0 + acol8]);
            ldmx4(al[0], &Al[(wm + arow) * LD + kc0 + acol8]);
            ldmx4(al[1], &Al[(wm + 16 + arow) * LD + kc0 + acol8]);
            unsigned bh[4][2], bl[4][2];
            {
                unsigned t0[4], t1[4];
                ldmx4(t0, &Wh[(wn + brow) * LD + kc0 + bcol8]);
                ldmx4(t1, &Wh[(wn + 16 + brow) * LD + kc0 + bcol8]);
                bh[0][0] = t0[0]; bh[0][1] = t0[1]; bh[1][0] = t0[2]; bh[1][1] = t0[3];
                bh[2][0] = t1[0]; bh[2][1] = t1[1]; bh[3][0] = t1[2]; bh[3][1] = t1[3];
                ldmx4(t0, &Wl[(wn + brow) * LD + kc0 + bcol8]);
                ldmx4(t1, &Wl[(wn + 16 + brow) * LD + kc0 + bcol8]);
                bl[0][0] = t0[0]; bl[0][1] = t0[1]; bl[1][0] = t0[2]; bl[1][1] = t0[3];
                bl[2][0] = t1[0]; bl[2][1] = t1[1]; bl[3][0] = t1[2]; bl[3][1] = t1[3];
            }
#pragma unroll
            for (int mi = 0; mi < 2; mi++)
#pragma unroll
                for (int ni = 0; ni < 4; ni++)
                    mma_bf16(acc[mi][ni], ah[mi], bh[ni][0], bh[ni][1]);
#pragma unroll
            for (int mi = 0; mi < 2; mi++)
#pragma unroll
                for (int ni = 0; ni < 4; ni++)
                    mma_bf16(acc[mi][ni], al[mi], bh[ni][0], bh[ni][1]);
#pragma unroll
            for (int mi = 0; mi < 2; mi++)
#pragma unroll
                for (int ni = 0; ni < 4; ni++)
                    mma_bf16(acc[mi][ni], ah[mi], bl[ni][0], bl[ni][1]);
        }
    }
#undef ISSUE_STAGE

    // epilogue
#pragma unroll
    for (int mi = 0; mi < 2; mi++)
#pragma unroll
        for (int ni = 0; ni < 4; ni++)
#pragma unroll
            for (int e = 0; e < 4; e++) {
                int row = m0 + wm + mi * 16 + g + ((e >= 2) ? 8 : 0);
                int col = n0 + wn + ni * 8 + 2 * t + (e & 1);
                float v = acc[mi][ni][e] + __ldg(&bias[col]);
                if (QKV_SCATTER) {
                    int which = col >> 10;          // 0=q,1=k,2=v
                    int c = col & (CC - 1);
                    int h = c >> 6, d = c & 63;
                    int b_ = row >> 11;
                    int tt = row & (TT - 1);
                    size_t dst = (((size_t)(b_ * HH + h) * TT + tt) * HD) + d;
                    float* base = (which == 0) ? g_q : ((which == 1) ? g_k : g_v);
                    base[dst] = v;
                } else {
                    Cout[(size_t)row * N + col] = v;
                }
            }
}

// ---------------------------------------------------------------------------
// Tensor-core flash attention (bf16 x3), 128-row Q tiles, 256 threads,
// 2 CTAs/SM. Unchanged from the passing Round-12 kernel.
// ---------------------------------------------------------------------------
__global__ __launch_bounds__(256, 2)
void attn_tc() {
    constexpr int LD = 72;
    extern __shared__ __nv_bfloat16 smb[];
    __nv_bfloat16* Khs = smb;                  // [64][72]
    __nv_bfloat16* Kls = Khs + 64 * LD;
    __nv_bfloat16* Vhs = Kls + 64 * LD;        // [64][72]
    __nv_bfloat16* Vls = Vhs + 64 * LD;
    __nv_bfloat16* Phs = Vls + 64 * LD;        // [128][72]
    __nv_bfloat16* Pls = Phs + 128 * LD;

    const int tid = threadIdx.x;
    const int lane = tid & 31, w = tid >> 5;
    const int g = lane >> 2, t = lane & 3;
    const int qi = (int)gridDim.x - 1 - (int)blockIdx.x;  // big tiles first
    const int bh_ = blockIdx.y;

    const float* Qg = g_q + (size_t)bh_ * TT * HD;
    const float* Kg = g_k + (size_t)bh_ * TT * HD;
    const float* Vg = g_v + (size_t)bh_ * TT * HD;

    const int qrow0 = qi * 128 + w * 16;

    const int arow = lane & 15, acol8 = (lane >> 4) << 3;
    const int brow = (lane & 7) + ((lane >> 4) << 3), bcol8 = lane & 8;
    const int rsel = lane & 15;

    unsigned qh[4][4], ql[4][4];
#pragma unroll
    for (int s = 0; s < 4; s++) {
        const int c0 = s * 16 + 2 * t;
        float2 x00 = *(const float2*)&Qg[(size_t)(qrow0 + g) * 64 + c0];
        float2 x01 = *(const float2*)&Qg[(size_t)(qrow0 + g) * 64 + c0 + 8];
        float2 x10 = *(const float2*)&Qg[(size_t)(qrow0 + g + 8) * 64 + c0];
        float2 x11 = *(const float2*)&Qg[(size_t)(qrow0 + g + 8) * 64 + c0 + 8];
        x00.x *= 0.125f; x00.y *= 0.125f; x01.x *= 0.125f; x01.y *= 0.125f;
        x10.x *= 0.125f; x10.y *= 0.125f; x11.x *= 0.125f; x11.y *= 0.125f;
        qh[s][0] = bfhi2(x00.x, x00.y); ql[s][0] = bflo2(x00.x, x00.y);
        qh[s][1] = bfhi2(x10.x, x10.y); ql[s][1] = bflo2(x10.x, x10.y);
        qh[s][2] = bfhi2(x01.x, x01.y); ql[s][2] = bflo2(x01.x, x01.y);
        qh[s][3] = bfhi2(x11.x, x11.y); ql[s][3] = bflo2(x11.x, x11.y);
    }

    float m0s = -1e30f, m1s = -1e30f, l0s = 0.f, l1s = 0.f;
    float O[8][4] = {};

    const int nkb = 2 * qi + 2;
    for (int kb = 0; kb < nkb; kb++) {
        const int k0 = kb * 64;
        __syncthreads();
#pragma unroll
        for (int i = 0; i < 4; i++) {
            int c = tid + 256 * i;
            int key = c >> 4, hd4 = (c & 15) * 4;
            uint2 h, l;
            split4bf(*(const float4*)&Kg[(size_t)(k0 + key) * 64 + hd4], h, l);
            *(uint2*)&Khs[key * LD + hd4] = h;
            *(uint2*)&Kls[key * LD + hd4] = l;
            split4bf(*(const float4*)&Vg[(size_t)(k0 + key) * 64 + hd4], h, l);
            *(uint2*)&Vhs[key * LD + hd4] = h;
            *(uint2*)&Vls[key * LD + hd4] = l;
        }
        __syncthreads();

        if (k0 <= qrow0 + 15) {
            float S[8][4] = {};
#pragma unroll
            for (int s = 0; s < 4; s++) {
                const int kc0 = s * 16;
#pragma unroll
                for (int nh = 0; nh < 2; nh++) {
                    unsigned bh4[2][4], bl4[2][4];
                    const int kr = nh * 32 + brow;
                    ldmx4(bh4[0], &Khs[kr * LD + kc0 + bcol8]);
                    ldmx4(bh4[1], &Khs[(kr + 16) * LD + kc0 + bcol8]);
                    ldmx4(bl4[0], &Kls[kr * LD + kc0 + bcol8]);
                    ldmx4(bl4[1], &Kls[(kr + 16) * LD + kc0 + bcol8]);
#pragma unroll
                    for (int j = 0; j < 4; j++)
                        mma_bf16(S[nh * 4 + j], qh[s],
                                 bh4[j >> 1][(j & 1) * 2], bh4[j >> 1][(j & 1) * 2 + 1]);
#pragma unroll
                    for (int j = 0; j < 4; j++)
                        mma_bf16(S[nh * 4 + j], ql[s],
                                 bh4[j >> 1][(j & 1) * 2], bh4[j >> 1][(j & 1) * 2 + 1]);
#pragma unroll
                    for (int j = 0; j < 4; j++)
                        mma_bf16(S[nh * 4 + j], qh[s],
                                 bl4[j >> 1][(j & 1) * 2], bl4[j >> 1][(j & 1) * 2 + 1]);
                }
            }
            if (k0 + 63 > qrow0) {
                int r0 = qrow0 + g, r1 = r0 + 8;
#pragma unroll
                for (int n = 0; n < 8; n++) {
                    int cb = k0 + n * 8 + 2 * t;
                    if (cb > r0)     S[n][0] = -1e30f;
                    if (cb + 1 > r0) S[n][1] = -1e30f;
                    if (cb > r1)     S[n][2] = -1e30f;
                    if (cb + 1 > r1) S[n][3] = -1e30f;
                }
            }
            float mx0 = -1e30f, mx1 = -1e30f;
#pragma unroll
            for (int n = 0; n < 8; n++) {
                mx0 = fmaxf(mx0, fmaxf(S[n][0], S[n][1]));
                mx1 = fmaxf(mx1, fmaxf(S[n][2], S[n][3]));
            }
            mx0 = fmaxf(mx0, __shfl_xor_sync(0xffffffffu, mx0, 1));
            mx0 = fmaxf(mx0, __shfl_xor_sync(0xffffffffu, mx0, 2));
            mx1 = fmaxf(mx1, __shfl_xor_sync(0xffffffffu, mx1, 1));
            mx1 = fmaxf(mx1, __shfl_xor_sync(0xffffffffu, mx1, 2));
            float mn0 = fmaxf(m0s, mx0), mn1 = fmaxf(m1s, mx1);
            float cr0 = __expf(m0s - mn0), cr1 = __expf(m1s - mn1);
            m0s = mn0; m1s = mn1;
            float rs0 = 0.f, rs1 = 0.f;
#pragma unroll
            for (int n = 0; n < 8; n++) {
                S[n][0] = __expf(S[n][0] - mn0);
                S[n][1] = __expf(S[n][1] - mn0);
                S[n][2] = __expf(S[n][2] - mn1);
                S[n][3] = __expf(S[n][3] - mn1);
                rs0 += S[n][0] + S[n][1];
                rs1 += S[n][2] + S[n][3];
            }
            rs0 += __shfl_xor_sync(0xffffffffu, rs0, 1);
            rs0 += __shfl_xor_sync(0xffffffffu, rs0, 2);
            rs1 += __shfl_xor_sync(0xffffffffu, rs1, 1);
            rs1 += __shfl_xor_sync(0xffffffffu, rs1, 2);
            l0s = l0s * cr0 + rs0;
            l1s = l1s * cr1 + rs1;
#pragma unroll
            for (int n = 0; n < 8; n++) {
                O[n][0] *= cr0; O[n][1] *= cr0;
                O[n][2] *= cr1; O[n][3] *= cr1;
            }
            const int pr0 = (w * 16 + g) * LD, pr1 = pr0 + 8 * LD;
#pragma unroll
            for (int n = 0; n < 8; n++) {
                const int pc = n * 8 + 2 * t;
                *(unsigned*)&Phs[pr0 + pc] = bfhi2(S[n][0], S[n][1]);
                *(unsigned*)&Pls[pr0 + pc] = bflo2(S[n][0], S[n][1]);
                *(unsigned*)&Phs[pr1 + pc] = bfhi2(S[n][2], S[n][3]);
                *(unsigned*)&Pls[pr1 + pc] = bflo2(S[n][2], S[n][3]);
            }
            __syncwarp();
#pragma unroll
            for (int s = 0; s < 4; s++) {
                unsigned pah[4], pal[4];
                ldmx4(pah, &Phs[(w * 16 + arow) * LD + s * 16 + acol8]);
                ldmx4(pal, &Pls[(w * 16 + arow) * LD + s * 16 + acol8]);
                const __nv_bfloat16* vrow_h = &Vhs[(s * 16 + rsel) * LD];
                const __nv_bfloat16* vrow_l = &Vls[(s * 16 + rsel) * LD];
#pragma unroll
                for (int nh = 0; nh < 2; nh++) {
                    unsigned vh[4][2], vl[4][2];
#pragma unroll
                    for (int j = 0; j < 4; j++) {
                        ldmx2t(vh[j][0], vh[j][1], vrow_h + (nh * 4 + j) * 8);
                        ldmx2t(vl[j][0], vl[j][1], vrow_l + (nh * 4 + j) * 8);
                    }
#pragma unroll
                    for (int j = 0; j < 4; j++)
                        mma_bf16(O[nh * 4 + j], pah, vh[j][0], vh[j][1]);
#pragma unroll
                    for (int j = 0; j < 4; j++)
                        mma_bf16(O[nh * 4 + j], pal, vh[j][0], vh[j][1]);
#pragma unroll
                    for (int j = 0; j < 4; j++)
                        mma_bf16(O[nh * 4 + j], pah, vl[j][0], vl[j][1]);
                }
            }
        }
    }

    // epilogue: write y as bf16 hi/lo planes (pairs are 2 consecutive cols)
    const int b_ = bh_ / HH, h = bh_ % HH;
    const float inv0 = 1.f / l0s, inv1 = 1.f / l1s;
    unsigned* yh = (unsigned*)g_yh;
    unsigned* yl = (unsigned*)g_yl;
#pragma unroll
    for (int n = 0; n < 8; n++) {
        int col = h * 64 + n * 8 + 2 * t;
        int r0 = qrow0 + g;
        size_t i0 = (((size_t)b_ * TT + r0) * CC + col) >> 1;
        size_t i1 = (((size_t)b_ * TT + r0 + 8) * CC + col) >> 1;
        float a0 = O[n][0] * inv0, a1 = O[n][1] * inv0;
        float a2 = O[n][2] * inv1, a3 = O[n][3] * inv1;
        yh[i0] = bfhi2(a0, a1); yl[i0] = bflo2(a0, a1);
        yh[i1] = bfhi2(a2, a3); yl[i1] = bflo2(a2, a3);
    }
}

// ---------------------------------------------------------------------------
// Launch: convert x/W -> qkv GEMM -> attention -> proj GEMM
// ---------------------------------------------------------------------------
static const int kGemmSmem = 3 * (2 * 64 * 40 + 2 * 128 * 40) * 2;   // 92160 B
static const int kAttnSmem = (4 * 64 * 72 + 2 * 128 * 72) * 2;       // 73728 B

extern "C" void kernel_launch(void* const* d_in, const int* in_sizes, int n_in,
                              void* d_out, int out_size) {
    const float* x      = (const float*)d_in[0];
    const float* W_attn = (const float*)d_in[1];
    const float* b_attn = (const float*)d_in[2];
    const float* W_proj = (const float*)d_in[3];
    const float* b_proj = (const float*)d_in[4];
    float* out = (float*)d_out;

    cudaFuncSetAttribute(gemm_cp<true>,
                         cudaFuncAttributeMaxDynamicSharedMemorySize, kGemmSmem);
    cudaFuncSetAttribute(gemm_cp<false>,
                         cudaFuncAttributeMaxDynamicSharedMemorySize, kGemmSmem);
    cudaFuncSetAttribute(attn_tc,
                         cudaFuncAttributeMaxDynamicSharedMemorySize, kAttnSmem);

    __nv_bfloat16 *xh, *xl, *wah, *wal, *wph, *wpl, *yh, *yl;
    cudaGetSymbolAddress((void**)&xh, g_xh);   cudaGetSymbolAddress((void**)&xl, g_xl);
    cudaGetSymbolAddress((void**)&wah, g_wah); cudaGetSymbolAddress((void**)&wal, g_wal);
    cudaGetSymbolAddress((void**)&wph, g_wph); cudaGetSymbolAddress((void**)&wpl, g_wpl);
    cudaGetSymbolAddress((void**)&yh, g_yh);   cudaGetSymbolAddress((void**)&yl, g_yl);

    // 0) convert inputs to bf16 hi/lo planes
    cvt_hilo<<<(MM * CC / 4) / 256, 256>>>(
        (const float4*)x, (uint2*)xh, (uint2*)xl, MM * CC / 4);
    cvt_hilo<<<(NQKV * CC / 4) / 256, 256>>>(
        (const float4*)W_attn, (uint2*)wah, (uint2*)wal, NQKV * CC / 4);
    cvt_hilo<<<(CC * CC / 4) / 256, 256>>>(
        (const float4*)W_proj, (uint2*)wph, (uint2*)wpl, CC * CC / 4);

    // 1) qkv projection (scatter into per-head q/k/v)
    gemm_cp<true><<<dim3(NQKV / 128, MM / 64), 256, kGemmSmem>>>(
        xh, xl, wah, wal, b_attn, nullptr, CC, NQKV);

    // 2) flash attention (writes y as bf16 hi/lo)
    attn_tc<<<dim3(TT / 128, BB * HH), 256, kAttnSmem>>>();

    // 3) output projection
    gemm_cp<false><<<dim3(CC / 128, MM / 64), 256, kGemmSmem>>>(
        yh, yl, wph, wpl, b_proj, out, CC, CC);
}

// round 14
// speedup vs baseline: 1.0924x; 1.0924x over previous
#include <cuda_runtime.h>
#include <cuda_bf16.h>
#include <math.h>

// Problem constants
#define BB 2
#define TT 2048
#define CC 1024
#define HH 16
#define HD 64
#define MM (BB*TT)        // 4096
#define NQKV (3*CC)       // 3072

// Scratch (device globals — allocation-free)
__device__ float g_q[(size_t)BB*HH*TT*HD];
// K/V stored pre-split as bf16 hi/lo planes, [B*H, T, HD]
__device__ __nv_bfloat16 g_kh[(size_t)BB*HH*TT*HD], g_kl[(size_t)BB*HH*TT*HD];
__device__ __nv_bfloat16 g_vh[(size_t)BB*HH*TT*HD], g_vl[(size_t)BB*HH*TT*HD];
// bf16 hi/lo planes for GEMM inputs
__device__ __nv_bfloat16 g_xh[(size_t)MM*CC],   g_xl[(size_t)MM*CC];
__device__ __nv_bfloat16 g_wah[(size_t)NQKV*CC], g_wal[(size_t)NQKV*CC];
__device__ __nv_bfloat16 g_wph[(size_t)CC*CC],  g_wpl[(size_t)CC*CC];
__device__ __nv_bfloat16 g_yh[(size_t)MM*CC],   g_yl[(size_t)MM*CC];

// ---------------------------------------------------------------------------
// Helpers
// ---------------------------------------------------------------------------
__device__ __forceinline__ unsigned bfhi2(float x, float y) {
    __nv_bfloat162 p = __floats2bfloat162_rn(x, y);
    return *(unsigned*)&p;
}
__device__ __forceinline__ unsigned bflo2(float x, float y) {
    float hx = __bfloat162float(__float2bfloat16_rn(x));
    float hy = __bfloat162float(__float2bfloat16_rn(y));
    return bfhi2(x - hx, y - hy);
}
__device__ __forceinline__ void split4bf(float4 v, uint2& h, uint2& l) {
    h.x = bfhi2(v.x, v.y); h.y = bfhi2(v.z, v.w);
    l.x = bflo2(v.x, v.y); l.y = bflo2(v.z, v.w);
}
__device__ __forceinline__ unsigned smem_u32(const void* p) {
    return (unsigned)__cvta_generic_to_shared(p);
}
__device__ __forceinline__ void mma_bf16(float d[4], const unsigned a[4],
                                         unsigned b0, unsigned b1) {
    asm volatile(
        "mma.sync.aligned.m16n8k16.row.col.f32.bf16.bf16.f32 "
        "{%0,%1,%2,%3}, {%4,%5,%6,%7}, {%8,%9}, {%0,%1,%2,%3};"
        : "+f"(d[0]), "+f"(d[1]), "+f"(d[2]), "+f"(d[3])
        : "r"(a[0]), "r"(a[1]), "r"(a[2]), "r"(a[3]), "r"(b0), "r"(b1));
}
__device__ __forceinline__ void ldmx4(unsigned r[4], const void* p) {
    unsigned addr = smem_u32(p);
    asm volatile("ldmatrix.sync.aligned.m8n8.x4.shared.b16 {%0,%1,%2,%3}, [%4];"
                 : "=r"(r[0]), "=r"(r[1]), "=r"(r[2]), "=r"(r[3]) : "r"(addr));
}
__device__ __forceinline__ void ldmx2t(unsigned& r0, unsigned& r1, const void* p) {
    unsigned addr = smem_u32(p);
    asm volatile("ldmatrix.sync.aligned.m8n8.x2.trans.shared.b16 {%0,%1}, [%2];"
                 : "=r"(r0), "=r"(r1) : "r"(addr));
}
__device__ __forceinline__ void cp_async16(unsigned dst, const void* src) {
    asm volatile("cp.async.cg.shared.global [%0], [%1], 16;"
                 :: "r"(dst), "l"(src) : "memory");
}
__device__ __forceinline__ void cp_commit() {
    asm volatile("cp.async.commit_group;" ::: "memory");
}

// ---------------------------------------------------------------------------
// Convert: fp32 -> bf16 hi/lo planes
// ---------------------------------------------------------------------------
__global__ void cvt_hilo(const float4* __restrict__ src, uint2* __restrict__ dh,
                         uint2* __restrict__ dl, int n4) {
    int i = blockIdx.x * blockDim.x + threadIdx.x;
    if (i < n4) {
        uint2 h, l;
        split4bf(src[i], h, l);
        dh[i] = h;
        dl[i] = l;
    }
}

// ---------------------------------------------------------------------------
// Pipelined bf16x3 GEMM (R12 config): out[m,n] = sum_k A[m,k]*W[n,k] + bias[n]
// 64x128 tile, BK=64, 2-stage cp.async, 256 threads = 8 warps (2x4),
// 32x32 per warp. smem 110592B/CTA -> 2 CTAs/SM.
// QKV_SCATTER epilogue: q -> fp32 g_q; k/v -> bf16 hi/lo planes.
// ---------------------------------------------------------------------------
template<bool QKV_SCATTER>
__global__ __launch_bounds__(256, 2)
void gemm_cp(const __nv_bfloat16* __restrict__ Agh, const __nv_bfloat16* __restrict__ Agl,
             const __nv_bfloat16* __restrict__ Wgh, const __nv_bfloat16* __restrict__ Wgl,
             const float* __restrict__ bias, float* __restrict__ Cout,
             int K, int N) {
    constexpr int BK = 64, LD = 72;
    constexpr int APLANE = 64 * LD;
    constexpr int WPLANE = 128 * LD;
    constexpr int STAGE = 2 * APLANE + 2 * WPLANE;
    extern __shared__ __nv_bfloat16 sm[];     // 2 * STAGE

    const int tid = threadIdx.x;
    const int lane = tid & 31, w = tid >> 5;
    const int g = lane >> 2, t = lane & 3;
    const int m0 = blockIdx.y * 64, n0 = blockIdx.x * 128;
    const int wm = (w >> 2) * 32, wn = (w & 3) * 32;

    const int arow = lane & 15, acol8 = (lane >> 4) << 3;
    const int brow = (lane & 7) + ((lane >> 4) << 3), bcol8 = lane & 8;

#define ISSUE_STAGE(sidx, kt)                                                  \
    do {                                                                       \
        __nv_bfloat16* sb = sm + (sidx) * STAGE;                               \
        _Pragma("unroll")                                                      \
        for (int rep = 0; rep < 2; rep++) {                                    \
            int c = tid + rep * 256;                                           \
            int row = c >> 3, c8 = c & 7;                                      \
            cp_async16(smem_u32(sb + row * LD + c8 * 8),                       \
                       Agh + (size_t)(m0 + row) * K + (kt) + c8 * 8);          \
            cp_async16(smem_u32(sb + APLANE + row * LD + c8 * 8),              \
                       Agl + (size_t)(m0 + row) * K + (kt) + c8 * 8);          \
        }                                                                      \
        _Pragma("unroll")                                                      \
        for (int rep = 0; rep < 4; rep++) {                                    \
            int c = tid + rep * 256;                                           \
            int row = c >> 3, c8 = c & 7;                                      \
            cp_async16(smem_u32(sb + 2 * APLANE + row * LD + c8 * 8),          \
                       Wgh + (size_t)(n0 + row) * K + (kt) + c8 * 8);          \
            cp_async16(smem_u32(sb + 2 * APLANE + WPLANE + row * LD + c8 * 8), \
                       Wgl + (size_t)(n0 + row) * K + (kt) + c8 * 8);          \
        }                                                                      \
        cp_commit();                                                           \
    } while (0)

    float acc[2][4][4] = {};

    const int niter = K / BK;                 // 16
    ISSUE_STAGE(0, 0);
    ISSUE_STAGE(1, BK);

    for (int it = 0; it < niter; it++) {
        if (it + 1 < niter)
            asm volatile("cp.async.wait_group 1;" ::: "memory");
        else
            asm volatile("cp.async.wait_group 0;" ::: "memory");
        __syncthreads();

        const __nv_bfloat16* Ah = sm + (it & 1) * STAGE;
        const __nv_bfloat16* Al = Ah + APLANE;
        const __nv_bfloat16* Wh = Al + APLANE;
        const __nv_bfloat16* Wl = Wh + WPLANE;

#pragma unroll
        for (int s = 0; s < 4; s++) {
            const int kc0 = s * 16;
            unsigned ah[2][4], al[2][4];
            ldmx4(ah[0], &Ah[(wm + arow) * LD + kc0 + acol8]);
            ldmx4(ah[1], &Ah[(wm + 16 + arow) * LD + kc0 + acol8]);
            ldmx4(al[0], &Al[(wm + arow) * LD + kc0 + acol8]);
            ldmx4(al[1], &Al[(wm + 16 + arow) * LD + kc0 + acol8]);
            unsigned bh[4][2], bl[4][2];
            {
                unsigned t0[4], t1[4];
                ldmx4(t0, &Wh[(wn + brow) * LD + kc0 + bcol8]);
                ldmx4(t1, &Wh[(wn + 16 + brow) * LD + kc0 + bcol8]);
                bh[0][0] = t0[0]; bh[0][1] = t0[1]; bh[1][0] = t0[2]; bh[1][1] = t0[3];
                bh[2][0] = t1[0]; bh[2][1] = t1[1]; bh[3][0] = t1[2]; bh[3][1] = t1[3];
                ldmx4(t0, &Wl[(wn + brow) * LD + kc0 + bcol8]);
                ldmx4(t1, &Wl[(wn + 16 + brow) * LD + kc0 + bcol8]);
                bl[0][0] = t0[0]; bl[0][1] = t0[1]; bl[1][0] = t0[2]; bl[1][1] = t0[3];
                bl[2][0] = t1[0]; bl[2][1] = t1[1]; bl[3][0] = t1[2]; bl[3][1] = t1[3];
            }
#pragma unroll
            for (int mi = 0; mi < 2; mi++)
#pragma unroll
                for (int ni = 0; ni < 4; ni++)
                    mma_bf16(acc[mi][ni], ah[mi], bh[ni][0], bh[ni][1]);
#pragma unroll
            for (int mi = 0; mi < 2; mi++)
#pragma unroll
                for (int ni = 0; ni < 4; ni++)
                    mma_bf16(acc[mi][ni], al[mi], bh[ni][0], bh[ni][1]);
#pragma unroll
            for (int mi = 0; mi < 2; mi++)
#pragma unroll
                for (int ni = 0; ni < 4; ni++)
                    mma_bf16(acc[mi][ni], ah[mi], bl[ni][0], bl[ni][1]);
        }
        __syncthreads();
        if (it + 2 < niter) ISSUE_STAGE((it + 2) & 1, (it + 2) * BK);
    }
#undef ISSUE_STAGE

    // epilogue (pairs: e=0,1 -> row, cols 2t/2t+1; e=2,3 -> row+8)
#pragma unroll
    for (int mi = 0; mi < 2; mi++)
#pragma unroll
        for (int ni = 0; ni < 4; ni++) {
            const int col = n0 + wn + ni * 8 + 2 * t;   // even
            const float b0f = __ldg(&bias[col]), b1f = __ldg(&bias[col + 1]);
            float v0 = acc[mi][ni][0] + b0f, v1 = acc[mi][ni][1] + b1f;
            float v2 = acc[mi][ni][2] + b0f, v3 = acc[mi][ni][3] + b1f;
            const int row0 = m0 + wm + mi * 16 + g, row1 = row0 + 8;
            if (QKV_SCATTER) {
                const int which = col >> 10;
                const int c = col & (CC - 1);
                const int h = c >> 6, d = c & 63;
#pragma unroll
                for (int rr = 0; rr < 2; rr++) {
                    int row = rr ? row1 : row0;
                    float a0 = rr ? v2 : v0, a1 = rr ? v3 : v1;
                    int b_ = row >> 11, tt = row & (TT - 1);
                    size_t base_i = ((size_t)(b_ * HH + h) * TT + tt) * HD + d;
                    if (which == 0) {
                        g_q[base_i] = a0;
                        g_q[base_i + 1] = a1;
                    } else {
                        size_t pi = base_i >> 1;
                        if (which == 1) {
                            ((unsigned*)g_kh)[pi] = bfhi2(a0, a1);
                            ((unsigned*)g_kl)[pi] = bflo2(a0, a1);
                        } else {
                            ((unsigned*)g_vh)[pi] = bfhi2(a0, a1);
                            ((unsigned*)g_vl)[pi] = bflo2(a0, a1);
                        }
                    }
                }
            } else {
                Cout[(size_t)row0 * N + col] = v0;
                Cout[(size_t)row0 * N + col + 1] = v1;
                Cout[(size_t)row1 * N + col] = v2;
                Cout[(size_t)row1 * N + col + 1] = v3;
            }
        }
}

// ---------------------------------------------------------------------------
// Tensor-core flash attention (bf16 x3), 128-row Q tiles, 256 threads,
// 2 CTAs/SM. K/V pre-split planes loaded via 2-stage cp.async (no cvt in loop).
// ---------------------------------------------------------------------------
__global__ __launch_bounds__(256, 2)
void attn_tc() {
    constexpr int LD = 72;
    constexpr int PL = 64 * LD;                // plane units
    constexpr int KVSTAGE = 4 * PL;            // Kh, Kl, Vh, Vl
    extern __shared__ __nv_bfloat16 smb[];     // 2*KVSTAGE + 2*128*LD
    __nv_bfloat16* Phs = smb + 2 * KVSTAGE;    // [128][72]
    __nv_bfloat16* Pls = Phs + 128 * LD;

    const int tid = threadIdx.x;
    const int lane = tid & 31, w = tid >> 5;
    const int g = lane >> 2, t = lane & 3;
    const int qi = (int)gridDim.x - 1 - (int)blockIdx.x;  // big tiles first
    const int bh_ = blockIdx.y;

    const float* Qg = g_q + (size_t)bh_ * TT * HD;
    const __nv_bfloat16* Kh_g = g_kh + (size_t)bh_ * TT * HD;
    const __nv_bfloat16* Kl_g = g_kl + (size_t)bh_ * TT * HD;
    const __nv_bfloat16* Vh_g = g_vh + (size_t)bh_ * TT * HD;
    const __nv_bfloat16* Vl_g = g_vl + (size_t)bh_ * TT * HD;

    const int qrow0 = qi * 128 + w * 16;

    const int arow = lane & 15, acol8 = (lane >> 4) << 3;
    const int brow = (lane & 7) + ((lane >> 4) << 3), bcol8 = lane & 8;
    const int rsel = lane & 15;

#define ISSUE_KV(sidx, k0v)                                                    \
    do {                                                                       \
        __nv_bfloat16* sb = smb + (sidx) * KVSTAGE;                            \
        _Pragma("unroll")                                                      \
        for (int rep = 0; rep < 2; rep++) {                                    \
            int c = tid + rep * 256;                                           \
            int row = c >> 3, c8 = c & 7;                                      \
            size_t goff = (size_t)((k0v) + row) * HD + c8 * 8;                 \
            unsigned so = row * LD + c8 * 8;                                   \
            cp_async16(smem_u32(sb + so), Kh_g + goff);                        \
            cp_async16(smem_u32(sb + PL + so), Kl_g + goff);                   \
            cp_async16(smem_u32(sb + 2 * PL + so), Vh_g + goff);               \
            cp_async16(smem_u32(sb + 3 * PL + so), Vl_g + goff);               \
        }                                                                      \
        cp_commit();                                                           \
    } while (0)

    unsigned qh[4][4], ql[4][4];
#pragma unroll
    for (int s = 0; s < 4; s++) {
        const int c0 = s * 16 + 2 * t;
        float2 x00 = *(const float2*)&Qg[(size_t)(qrow0 + g) * 64 + c0];
        float2 x01 = *(const float2*)&Qg[(size_t)(qrow0 + g) * 64 + c0 + 8];
        float2 x10 = *(const float2*)&Qg[(size_t)(qrow0 + g + 8) * 64 + c0];
        float2 x11 = *(const float2*)&Qg[(size_t)(qrow0 + g + 8) * 64 + c0 + 8];
        x00.x *= 0.125f; x00.y *= 0.125f; x01.x *= 0.125f; x01.y *= 0.125f;
        x10.x *= 0.125f; x10.y *= 0.125f; x11.x *= 0.125f; x11.y *= 0.125f;
        qh[s][0] = bfhi2(x00.x, x00.y); ql[s][0] = bflo2(x00.x, x00.y);
        qh[s][1] = bfhi2(x10.x, x10.y); ql[s][1] = bflo2(x10.x, x10.y);
        qh[s][2] = bfhi2(x01.x, x01.y); ql[s][2] = bflo2(x01.x, x01.y);
        qh[s][3] = bfhi2(x11.x, x11.y); ql[s][3] = bflo2(x11.x, x11.y);
    }

    float m0s = -1e30f, m1s = -1e30f, l0s = 0.f, l1s = 0.f;
    float O[8][4] = {};

    const int nkb = 2 * qi + 2;
    ISSUE_KV(0, 0);
    ISSUE_KV(1, 64);

    for (int kb = 0; kb < nkb; kb++) {
        const int k0 = kb * 64;
        if (kb + 1 < nkb)
            asm volatile("cp.async.wait_group 1;" ::: "memory");
        else
            asm volatile("cp.async.wait_group 0;" ::: "memory");
        __syncthreads();

        const __nv_bfloat16* Khs = smb + (kb & 1) * KVSTAGE;
        const __nv_bfloat16* Kls = Khs + PL;
        const __nv_bfloat16* Vhs = Kls + PL;
        const __nv_bfloat16* Vls = Vhs + PL;

        if (k0 <= qrow0 + 15) {
            float S[8][4] = {};
#pragma unroll
            for (int s = 0; s < 4; s++) {
                const int kc0 = s * 16;
#pragma unroll
                for (int nh = 0; nh < 2; nh++) {
                    unsigned bh4[2][4], bl4[2][4];
                    const int kr = nh * 32 + brow;
                    ldmx4(bh4[0], &Khs[kr * LD + kc0 + bcol8]);
                    ldmx4(bh4[1], &Khs[(kr + 16) * LD + kc0 + bcol8]);
                    ldmx4(bl4[0], &Kls[kr * LD + kc0 + bcol8]);
                    ldmx4(bl4[1], &Kls[(kr + 16) * LD + kc0 + bcol8]);
#pragma unroll
                    for (int j = 0; j < 4; j++)
                        mma_bf16(S[nh * 4 + j], qh[s],
                                 bh4[j >> 1][(j & 1) * 2], bh4[j >> 1][(j & 1) * 2 + 1]);
#pragma unroll
                    for (int j = 0; j < 4; j++)
                        mma_bf16(S[nh * 4 + j], ql[s],
                                 bh4[j >> 1][(j & 1) * 2], bh4[j >> 1][(j & 1) * 2 + 1]);
#pragma unroll
                    for (int j = 0; j < 4; j++)
                        mma_bf16(S[nh * 4 + j], qh[s],
                                 bl4[j >> 1][(j & 1) * 2], bl4[j >> 1][(j & 1) * 2 + 1]);
                }
            }
            if (k0 + 63 > qrow0) {
                int r0 = qrow0 + g, r1 = r0 + 8;
#pragma unroll
                for (int n = 0; n < 8; n++) {
                    int cb = k0 + n * 8 + 2 * t;
                    if (cb > r0)     S[n][0] = -1e30f;
                    if (cb + 1 > r0) S[n][1] = -1e30f;
                    if (cb > r1)     S[n][2] = -1e30f;
                    if (cb + 1 > r1) S[n][3] = -1e30f;
                }
            }
            float mx0 = -1e30f, mx1 = -1e30f;
#pragma unroll
            for (int n = 0; n < 8; n++) {
                mx0 = fmaxf(mx0, fmaxf(S[n][0], S[n][1]));
                mx1 = fmaxf(mx1, fmaxf(S[n][2], S[n][3]));
            }
            mx0 = fmaxf(mx0, __shfl_xor_sync(0xffffffffu, mx0, 1));
            mx0 = fmaxf(mx0, __shfl_xor_sync(0xffffffffu, mx0, 2));
            mx1 = fmaxf(mx1, __shfl_xor_sync(0xffffffffu, mx1, 1));
            mx1 = fmaxf(mx1, __shfl_xor_sync(0xffffffffu, mx1, 2));
            float mn0 = fmaxf(m0s, mx0), mn1 = fmaxf(m1s, mx1);
            float cr0 = __expf(m0s - mn0), cr1 = __expf(m1s - mn1);
            m0s = mn0; m1s = mn1;
            float rs0 = 0.f, rs1 = 0.f;
#pragma unroll
            for (int n = 0; n < 8; n++) {
                S[n][0] = __expf(S[n][0] - mn0);
                S[n][1] = __expf(S[n][1] - mn0);
                S[n][2] = __expf(S[n][2] - mn1);
                S[n][3] = __expf(S[n][3] - mn1);
                rs0 += S[n][0] + S[n][1];
                rs1 += S[n][2] + S[n][3];
            }
            rs0 += __shfl_xor_sync(0xffffffffu, rs0, 1);
            rs0 += __shfl_xor_sync(0xffffffffu, rs0, 2);
            rs1 += __shfl_xor_sync(0xffffffffu, rs1, 1);
            rs1 += __shfl_xor_sync(0xffffffffu, rs1, 2);
            l0s = l0s * cr0 + rs0;
            l1s = l1s * cr1 + rs1;
#pragma unroll
            for (int n = 0; n < 8; n++) {
                O[n][0] *= cr0; O[n][1] *= cr0;
                O[n][2] *= cr1; O[n][3] *= cr1;
            }
            const int pr0 = (w * 16 + g) * LD, pr1 = pr0 + 8 * LD;
#pragma unroll
            for (int n = 0; n < 8; n++) {
                const int pc = n * 8 + 2 * t;
                *(unsigned*)&Phs[pr0 + pc] = bfhi2(S[n][0], S[n][1]);
                *(unsigned*)&Pls[pr0 + pc] = bflo2(S[n][0], S[n][1]);
                *(unsigned*)&Phs[pr1 + pc] = bfhi2(S[n][2], S[n][3]);
                *(unsigned*)&Pls[pr1 + pc] = bflo2(S[n][2], S[n][3]);
            }
            __syncwarp();
#pragma unroll
            for (int s = 0; s < 4; s++) {
                unsigned pah[4], pal[4];
                ldmx4(pah, &Phs[(w * 16 + arow) * LD + s * 16 + acol8]);
                ldmx4(pal, &Pls[(w * 16 + arow) * LD + s * 16 + acol8]);
                const __nv_bfloat16* vrow_h = &Vhs[(s * 16 + rsel) * LD];
                const __nv_bfloat16* vrow_l = &Vls[(s * 16 + rsel) * LD];
#pragma unroll
                for (int nh = 0; nh < 2; nh++) {
                    unsigned vh[4][2], vl[4][2];
#pragma unroll
                    for (int j = 0; j < 4; j++) {
                        ldmx2t(vh[j][0], vh[j][1], vrow_h + (nh * 4 + j) * 8);
                        ldmx2t(vl[j][0], vl[j][1], vrow_l + (nh * 4 + j) * 8);
                    }
#pragma unroll
                    for (int j = 0; j < 4; j++)
                        mma_bf16(O[nh * 4 + j], pah, vh[j][0], vh[j][1]);
#pragma unroll
                    for (int j = 0; j < 4; j++)
                        mma_bf16(O[nh * 4 + j], pal, vh[j][0], vh[j][1]);
#pragma unroll
                    for (int j = 0; j < 4; j++)
                        mma_bf16(O[nh * 4 + j], pah, vl[j][0], vl[j][1]);
                }
            }
        }
        __syncthreads();                       // done reading buffer (kb&1)
        if (kb + 2 < nkb) ISSUE_KV(kb & 1, (kb + 2) * 64);
    }
#undef ISSUE_KV

    // epilogue: write y as bf16 hi/lo planes
    const int b_ = bh_ / HH, h = bh_ % HH;
    const float inv0 = 1.f / l0s, inv1 = 1.f / l1s;
    unsigned* yh = (unsigned*)g_yh;
    unsigned* yl = (unsigned*)g_yl;
#pragma unroll
    for (int n = 0; n < 8; n++) {
        int col = h * 64 + n * 8 + 2 * t;
        int r0 = qrow0 + g;
        size_t i0 = (((size_t)b_ * TT + r0) * CC + col) >> 1;
        size_t i1 = (((size_t)b_ * TT + r0 + 8) * CC + col) >> 1;
        float a0 = O[n][0] * inv0, a1 = O[n][1] * inv0;
        float a2 = O[n][2] * inv1, a3 = O[n][3] * inv1;
        yh[i0] = bfhi2(a0, a1); yl[i0] = bflo2(a0, a1);
        yh[i1] = bfhi2(a2, a3); yl[i1] = bflo2(a2, a3);
    }
}

// ---------------------------------------------------------------------------
// Launch: convert x/W -> qkv GEMM -> attention -> proj GEMM
// ---------------------------------------------------------------------------
static const int kGemmSmem = 2 * (2 * 64 * 72 + 2 * 128 * 72) * 2;   // 110592 B
static const int kAttnSmem = (2 * 4 * 64 * 72 + 2 * 128 * 72) * 2;   // 110592 B

extern "C" void kernel_launch(void* const* d_in, const int* in_sizes, int n_in,
                              void* d_out, int out_size) {
    const float* x      = (const float*)d_in[0];
    const float* W_attn = (const float*)d_in[1];
    const float* b_attn = (const float*)d_in[2];
    const float* W_proj = (const float*)d_in[3];
    const float* b_proj = (const float*)d_in[4];
    float* out = (float*)d_out;

    cudaFuncSetAttribute(gemm_cp<true>,
                         cudaFuncAttributeMaxDynamicSharedMemorySize, kGemmSmem);
    cudaFuncSetAttribute(gemm_cp<false>,
                         cudaFuncAttributeMaxDynamicSharedMemorySize, kGemmSmem);
    cudaFuncSetAttribute(attn_tc,
                         cudaFuncAttributeMaxDynamicSharedMemorySize, kAttnSmem);

    __nv_bfloat16 *xh, *xl, *wah, *wal, *wph, *wpl, *yh, *yl;
    cudaGetSymbolAddress((void**)&xh, g_xh);   cudaGetSymbolAddress((void**)&xl, g_xl);
    cudaGetSymbolAddress((void**)&wah, g_wah); cudaGetSymbolAddress((void**)&wal, g_wal);
    cudaGetSymbolAddress((void**)&wph, g_wph); cudaGetSymbolAddress((void**)&wpl, g_wpl);
    cudaGetSymbolAddress((void**)&yh, g_yh);   cudaGetSymbolAddress((void**)&yl, g_yl);

    // 0) convert inputs to bf16 hi/lo planes
    cvt_hilo<<<(MM * CC / 4) / 256, 256>>>(
        (const float4*)x, (uint2*)xh, (uint2*)xl, MM * CC / 4);
    cvt_hilo<<<(NQKV * CC / 4) / 256, 256>>>(
        (const float4*)W_attn, (uint2*)wah, (uint2*)wal, NQKV * CC / 4);
    cvt_hilo<<<(CC * CC / 4) / 256, 256>>>(
        (const float4*)W_proj, (uint2*)wph, (uint2*)wpl, CC * CC / 4);

    // 1) qkv projection (q -> fp32, k/v -> bf16 hi/lo planes)
    gemm_cp<true><<<dim3(NQKV / 128, MM / 64), 256, kGemmSmem>>>(
        xh, xl, wah, wal, b_attn, nullptr, CC, NQKV);

    // 2) flash attention (cp.async K/V, writes y as bf16 hi/lo)
    attn_tc<<<dim3(TT / 128, BB * HH), 256, kAttnSmem>>>();

    // 3) output projection
    gemm_cp<false><<<dim3(CC / 128, MM / 64), 256, kGemmSmem>>>(
        yh, yl, wph, wpl, b_proj, out, CC, CC);
}

// round 15
// speedup vs baseline: 1.4920x; 1.3657x over previous
#include <cuda_runtime.h>
#include <cuda_fp16.h>
#include <math.h>

// Problem constants
#define BB 2
#define TT 2048
#define CC 1024
#define HH 16
#define HD 64
#define MM (BB*TT)        // 4096
#define NQKV (3*CC)       // 3072

// Scratch (device globals — allocation-free)
__device__ float g_q[(size_t)BB*HH*TT*HD];
// K/V stored as fp16 hi plane only, [B*H, T, HD]
__device__ __half g_kh[(size_t)BB*HH*TT*HD];
__device__ __half g_vh[(size_t)BB*HH*TT*HD];
// fp16 planes for GEMM inputs (A operands hi+lo, W operands hi only)
__device__ __half g_xh[(size_t)MM*CC],   g_xl[(size_t)MM*CC];
__device__ __half g_wah[(size_t)NQKV*CC];
__device__ __half g_wph[(size_t)CC*CC];
__device__ __half g_yh[(size_t)MM*CC],   g_yl[(size_t)MM*CC];

// ---------------------------------------------------------------------------
// Helpers (fp16 hi/lo packing)
// ---------------------------------------------------------------------------
__device__ __forceinline__ unsigned h2hi(float x, float y) {
    __half2 p = __floats2half2_rn(x, y);
    return *(unsigned*)&p;
}
__device__ __forceinline__ unsigned h2lo(float x, float y) {
    float hx = __half2float(__float2half_rn(x));
    float hy = __half2float(__float2half_rn(y));
    return h2hi(x - hx, y - hy);
}
__device__ __forceinline__ void split4h(float4 v, uint2& h, uint2& l) {
    h.x = h2hi(v.x, v.y); h.y = h2hi(v.z, v.w);
    l.x = h2lo(v.x, v.y); l.y = h2lo(v.z, v.w);
}
__device__ __forceinline__ void hi4(float4 v, uint2& h) {
    h.x = h2hi(v.x, v.y); h.y = h2hi(v.z, v.w);
}
__device__ __forceinline__ unsigned smem_u32(const void* p) {
    return (unsigned)__cvta_generic_to_shared(p);
}
__device__ __forceinline__ void mma_f16(float d[4], const unsigned a[4],
                                        unsigned b0, unsigned b1) {
    asm volatile(
        "mma.sync.aligned.m16n8k16.row.col.f32.f16.f16.f32 "
        "{%0,%1,%2,%3}, {%4,%5,%6,%7}, {%8,%9}, {%0,%1,%2,%3};"
        : "+f"(d[0]), "+f"(d[1]), "+f"(d[2]), "+f"(d[3])
        : "r"(a[0]), "r"(a[1]), "r"(a[2]), "r"(a[3]), "r"(b0), "r"(b1));
}
__device__ __forceinline__ void ldmx4(unsigned r[4], const void* p) {
    unsigned addr = smem_u32(p);
    asm volatile("ldmatrix.sync.aligned.m8n8.x4.shared.b16 {%0,%1,%2,%3}, [%4];"
                 : "=r"(r[0]), "=r"(r[1]), "=r"(r[2]), "=r"(r[3]) : "r"(addr));
}
__device__ __forceinline__ void ldmx2t(unsigned& r0, unsigned& r1, const void* p) {
    unsigned addr = smem_u32(p);
    asm volatile("ldmatrix.sync.aligned.m8n8.x2.trans.shared.b16 {%0,%1}, [%2];"
                 : "=r"(r0), "=r"(r1) : "r"(addr));
}
__device__ __forceinline__ void cp_async16(unsigned dst, const void* src) {
    asm volatile("cp.async.cg.shared.global [%0], [%1], 16;"
                 :: "r"(dst), "l"(src) : "memory");
}
__device__ __forceinline__ void cp_commit() {
    asm volatile("cp.async.commit_group;" ::: "memory");
}

// ---------------------------------------------------------------------------
// Converts: fp32 -> fp16 planes
// ---------------------------------------------------------------------------
__global__ void cvt_hl(const float4* __restrict__ src, uint2* __restrict__ dh,
                       uint2* __restrict__ dl, int n4) {
    int i = blockIdx.x * blockDim.x + threadIdx.x;
    if (i < n4) {
        uint2 h, l;
        split4h(src[i], h, l);
        dh[i] = h;
        dl[i] = l;
    }
}
__global__ void cvt_h(const float4* __restrict__ src, uint2* __restrict__ dh, int n4) {
    int i = blockIdx.x * blockDim.x + threadIdx.x;
    if (i < n4) {
        uint2 h;
        hi4(src[i], h);
        dh[i] = h;
    }
}

// ---------------------------------------------------------------------------
// Pipelined fp16 x2 GEMM: out[m,n] = sum_k A[m,k]*W[n,k] + bias[n]
// A = Ah+Al (22-bit), W = Wh (11-bit). Products: ah*wh + al*wh.
// 64x128 tile, BK=64, 2-stage cp.async, 256 threads = 8 warps (2x4),
// 32x32 per warp. smem 73728B/CTA -> 2 CTAs/SM.
// ---------------------------------------------------------------------------
template<bool QKV_SCATTER>
__global__ __launch_bounds__(256, 2)
void gemm_cp(const __half* __restrict__ Agh, const __half* __restrict__ Agl,
             const __half* __restrict__ Wgh,
             const float* __restrict__ bias, float* __restrict__ Cout,
             int K, int N) {
    constexpr int BK = 64, LD = 72;
    constexpr int APLANE = 64 * LD;
    constexpr int WPLANE = 128 * LD;
    constexpr int STAGE = 2 * APLANE + WPLANE;   // Ah, Al, Wh
    extern __shared__ __half sm[];               // 2 * STAGE

    const int tid = threadIdx.x;
    const int lane = tid & 31, w = tid >> 5;
    const int g = lane >> 2, t = lane & 3;
    const int m0 = blockIdx.y * 64, n0 = blockIdx.x * 128;
    const int wm = (w >> 2) * 32, wn = (w & 3) * 32;

    const int arow = lane & 15, acol8 = (lane >> 4) << 3;
    const int brow = (lane & 7) + ((lane >> 4) << 3), bcol8 = lane & 8;

#define ISSUE_STAGE(sidx, kt)                                                  \
    do {                                                                       \
        __half* sb = sm + (sidx) * STAGE;                                      \
        _Pragma("unroll")                                                      \
        for (int rep = 0; rep < 2; rep++) {  /* A hi+lo: 512 chunks each */    \
            int c = tid + rep * 256;                                           \
            int row = c >> 3, c8 = c & 7;                                      \
            cp_async16(smem_u32(sb + row * LD + c8 * 8),                       \
                       Agh + (size_t)(m0 + row) * K + (kt) + c8 * 8);          \
            cp_async16(smem_u32(sb + APLANE + row * LD + c8 * 8),              \
                       Agl + (size_t)(m0 + row) * K + (kt) + c8 * 8);          \
        }                                                                      \
        _Pragma("unroll")                                                      \
        for (int rep = 0; rep < 4; rep++) {  /* W hi: 1024 chunks */           \
            int c = tid + rep * 256;                                           \
            int row = c >> 3, c8 = c & 7;                                      \
            cp_async16(smem_u32(sb + 2 * APLANE + row * LD + c8 * 8),          \
                       Wgh + (size_t)(n0 + row) * K + (kt) + c8 * 8);          \
        }                                                                      \
        cp_commit();                                                           \
    } while (0)

    float acc[2][4][4] = {};

    const int niter = K / BK;                 // 16
    ISSUE_STAGE(0, 0);
    ISSUE_STAGE(1, BK);

    for (int it = 0; it < niter; it++) {
        if (it + 1 < niter)
            asm volatile("cp.async.wait_group 1;" ::: "memory");
        else
            asm volatile("cp.async.wait_group 0;" ::: "memory");
        __syncthreads();

        const __half* Ah = sm + (it & 1) * STAGE;
        const __half* Al = Ah + APLANE;
        const __half* Wh = Al + APLANE;

#pragma unroll
        for (int s = 0; s < 4; s++) {
            const int kc0 = s * 16;
            unsigned ah[2][4], al[2][4];
            ldmx4(ah[0], &Ah[(wm + arow) * LD + kc0 + acol8]);
            ldmx4(ah[1], &Ah[(wm + 16 + arow) * LD + kc0 + acol8]);
            ldmx4(al[0], &Al[(wm + arow) * LD + kc0 + acol8]);
            ldmx4(al[1], &Al[(wm + 16 + arow) * LD + kc0 + acol8]);
            unsigned bh[4][2];
            {
                unsigned t0[4], t1[4];
                ldmx4(t0, &Wh[(wn + brow) * LD + kc0 + bcol8]);
                ldmx4(t1, &Wh[(wn + 16 + brow) * LD + kc0 + bcol8]);
                bh[0][0] = t0[0]; bh[0][1] = t0[1]; bh[1][0] = t0[2]; bh[1][1] = t0[3];
                bh[2][0] = t1[0]; bh[2][1] = t1[1]; bh[3][0] = t1[2]; bh[3][1] = t1[3];
            }
            // product-major: all 8 accumulators per product
#pragma unroll
            for (int mi = 0; mi < 2; mi++)
#pragma unroll
                for (int ni = 0; ni < 4; ni++)
                    mma_f16(acc[mi][ni], ah[mi], bh[ni][0], bh[ni][1]);
#pragma unroll
            for (int mi = 0; mi < 2; mi++)
#pragma unroll
                for (int ni = 0; ni < 4; ni++)
                    mma_f16(acc[mi][ni], al[mi], bh[ni][0], bh[ni][1]);
        }
        __syncthreads();
        if (it + 2 < niter) ISSUE_STAGE((it + 2) & 1, (it + 2) * BK);
    }
#undef ISSUE_STAGE

    // epilogue
#pragma unroll
    for (int mi = 0; mi < 2; mi++)
#pragma unroll
        for (int ni = 0; ni < 4; ni++) {
            const int col = n0 + wn + ni * 8 + 2 * t;   // even
            const float b0f = __ldg(&bias[col]), b1f = __ldg(&bias[col + 1]);
            float v0 = acc[mi][ni][0] + b0f, v1 = acc[mi][ni][1] + b1f;
            float v2 = acc[mi][ni][2] + b0f, v3 = acc[mi][ni][3] + b1f;
            const int row0 = m0 + wm + mi * 16 + g, row1 = row0 + 8;
            if (QKV_SCATTER) {
                const int which = col >> 10;
                const int c = col & (CC - 1);
                const int h = c >> 6, d = c & 63;
#pragma unroll
                for (int rr = 0; rr < 2; rr++) {
                    int row = rr ? row1 : row0;
                    float a0 = rr ? v2 : v0, a1 = rr ? v3 : v1;
                    int b_ = row >> 11, tt = row & (TT - 1);
                    size_t base_i = ((size_t)(b_ * HH + h) * TT + tt) * HD + d;
                    if (which == 0) {
                        g_q[base_i] = a0;
                        g_q[base_i + 1] = a1;
                    } else {
                        size_t pi = base_i >> 1;
                        if (which == 1) ((unsigned*)g_kh)[pi] = h2hi(a0, a1);
                        else            ((unsigned*)g_vh)[pi] = h2hi(a0, a1);
                    }
                }
            } else {
                Cout[(size_t)row0 * N + col] = v0;
                Cout[(size_t)row0 * N + col + 1] = v1;
                Cout[(size_t)row1 * N + col] = v2;
                Cout[(size_t)row1 * N + col + 1] = v3;
            }
        }
}

// ---------------------------------------------------------------------------
// Tensor-core flash attention (fp16 x2), 128-row Q tiles, 256 threads,
// 2 CTAs/SM. Q = qh+ql, K = hi only; P = ph+pl, V = hi only.
// K/V planes loaded via 2-stage cp.async.
// ---------------------------------------------------------------------------
__global__ __launch_bounds__(256, 2)
void attn_tc() {
    constexpr int LD = 72;
    constexpr int PL = 64 * LD;                // plane units
    constexpr int KVSTAGE = 2 * PL;            // Kh, Vh
    extern __shared__ __half smb[];            // 2*KVSTAGE + 2*128*LD
    __half* Phs = smb + 2 * KVSTAGE;           // [128][72]
    __half* Pls = Phs + 128 * LD;

    const int tid = threadIdx.x;
    const int lane = tid & 31, w = tid >> 5;
    const int g = lane >> 2, t = lane & 3;
    const int qi = (int)gridDim.x - 1 - (int)blockIdx.x;  // big tiles first
    const int bh_ = blockIdx.y;

    const float* Qg = g_q + (size_t)bh_ * TT * HD;
    const __half* Kh_g = g_kh + (size_t)bh_ * TT * HD;
    const __half* Vh_g = g_vh + (size_t)bh_ * TT * HD;

    const int qrow0 = qi * 128 + w * 16;

    const int arow = lane & 15, acol8 = (lane >> 4) << 3;
    const int brow = (lane & 7) + ((lane >> 4) << 3), bcol8 = lane & 8;
    const int rsel = lane & 15;

#define ISSUE_KV(sidx, k0v)                                                    \
    do {                                                                       \
        __half* sb = smb + (sidx) * KVSTAGE;                                   \
        _Pragma("unroll")                                                      \
        for (int rep = 0; rep < 2; rep++) {                                    \
            int c = tid + rep * 256;                                           \
            int row = c >> 3, c8 = c & 7;                                      \
            size_t goff = (size_t)((k0v) + row) * HD + c8 * 8;                 \
            unsigned so = row * LD + c8 * 8;                                   \
            cp_async16(smem_u32(sb + so), Kh_g + goff);                        \
            cp_async16(smem_u32(sb + PL + so), Vh_g + goff);                   \
        }                                                                      \
        cp_commit();                                                           \
    } while (0)

    unsigned qh[4][4], ql[4][4];
#pragma unroll
    for (int s = 0; s < 4; s++) {
        const int c0 = s * 16 + 2 * t;
        float2 x00 = *(const float2*)&Qg[(size_t)(qrow0 + g) * 64 + c0];
        float2 x01 = *(const float2*)&Qg[(size_t)(qrow0 + g) * 64 + c0 + 8];
        float2 x10 = *(const float2*)&Qg[(size_t)(qrow0 + g + 8) * 64 + c0];
        float2 x11 = *(const float2*)&Qg[(size_t)(qrow0 + g + 8) * 64 + c0 + 8];
        x00.x *= 0.125f; x00.y *= 0.125f; x01.x *= 0.125f; x01.y *= 0.125f;
        x10.x *= 0.125f; x10.y *= 0.125f; x11.x *= 0.125f; x11.y *= 0.125f;
        qh[s][0] = h2hi(x00.x, x00.y); ql[s][0] = h2lo(x00.x, x00.y);
        qh[s][1] = h2hi(x10.x, x10.y); ql[s][1] = h2lo(x10.x, x10.y);
        qh[s][2] = h2hi(x01.x, x01.y); ql[s][2] = h2lo(x01.x, x01.y);
        qh[s][3] = h2hi(x11.x, x11.y); ql[s][3] = h2lo(x11.x, x11.y);
    }

    float m0s = -1e30f, m1s = -1e30f, l0s = 0.f, l1s = 0.f;
    float O[8][4] = {};

    const int nkb = 2 * qi + 2;
    ISSUE_KV(0, 0);
    ISSUE_KV(1, 64);

    for (int kb = 0; kb < nkb; kb++) {
        const int k0 = kb * 64;
        if (kb + 1 < nkb)
            asm volatile("cp.async.wait_group 1;" ::: "memory");
        else
            asm volatile("cp.async.wait_group 0;" ::: "memory");
        __syncthreads();

        const __half* Khs = smb + (kb & 1) * KVSTAGE;
        const __half* Vhs = Khs + PL;

        if (k0 <= qrow0 + 15) {
            float S[8][4] = {};
#pragma unroll
            for (int s = 0; s < 4; s++) {
                const int kc0 = s * 16;
#pragma unroll
                for (int nh = 0; nh < 2; nh++) {
                    unsigned bh4[2][4];
                    const int kr = nh * 32 + brow;
                    ldmx4(bh4[0], &Khs[kr * LD + kc0 + bcol8]);
                    ldmx4(bh4[1], &Khs[(kr + 16) * LD + kc0 + bcol8]);
#pragma unroll
                    for (int j = 0; j < 4; j++)
                        mma_f16(S[nh * 4 + j], qh[s],
                                bh4[j >> 1][(j & 1) * 2], bh4[j >> 1][(j & 1) * 2 + 1]);
#pragma unroll
                    for (int j = 0; j < 4; j++)
                        mma_f16(S[nh * 4 + j], ql[s],
                                bh4[j >> 1][(j & 1) * 2], bh4[j >> 1][(j & 1) * 2 + 1]);
                }
            }
            if (k0 + 63 > qrow0) {
                int r0 = qrow0 + g, r1 = r0 + 8;
#pragma unroll
                for (int n = 0; n < 8; n++) {
                    int cb = k0 + n * 8 + 2 * t;
                    if (cb > r0)     S[n][0] = -1e30f;
                    if (cb + 1 > r0) S[n][1] = -1e30f;
                    if (cb > r1)     S[n][2] = -1e30f;
                    if (cb + 1 > r1) S[n][3] = -1e30f;
                }
            }
            float mx0 = -1e30f, mx1 = -1e30f;
#pragma unroll
            for (int n = 0; n < 8; n++) {
                mx0 = fmaxf(mx0, fmaxf(S[n][0], S[n][1]));
                mx1 = fmaxf(mx1, fmaxf(S[n][2], S[n][3]));
            }
            mx0 = fmaxf(mx0, __shfl_xor_sync(0xffffffffu, mx0, 1));
            mx0 = fmaxf(mx0, __shfl_xor_sync(0xffffffffu, mx0, 2));
            mx1 = fmaxf(mx1, __shfl_xor_sync(0xffffffffu, mx1, 1));
            mx1 = fmaxf(mx1, __shfl_xor_sync(0xffffffffu, mx1, 2));
            float mn0 = fmaxf(m0s, mx0), mn1 = fmaxf(m1s, mx1);
            float cr0 = __expf(m0s - mn0), cr1 = __expf(m1s - mn1);
            m0s = mn0; m1s = mn1;
            float rs0 = 0.f, rs1 = 0.f;
#pragma unroll
            for (int n = 0; n < 8; n++) {
                S[n][0] = __expf(S[n][0] - mn0);
                S[n][1] = __expf(S[n][1] - mn0);
                S[n][2] = __expf(S[n][2] - mn1);
                S[n][3] = __expf(S[n][3] - mn1);
                rs0 += S[n][0] + S[n][1];
                rs1 += S[n][2] + S[n][3];
            }
            rs0 += __shfl_xor_sync(0xffffffffu, rs0, 1);
            rs0 += __shfl_xor_sync(0xffffffffu, rs0, 2);
            rs1 += __shfl_xor_sync(0xffffffffu, rs1, 1);
            rs1 += __shfl_xor_sync(0xffffffffu, rs1, 2);
            l0s = l0s * cr0 + rs0;
            l1s = l1s * cr1 + rs1;
#pragma unroll
            for (int n = 0; n < 8; n++) {
                O[n][0] *= cr0; O[n][1] *= cr0;
                O[n][2] *= cr1; O[n][3] *= cr1;
            }
            const int pr0 = (w * 16 + g) * LD, pr1 = pr0 + 8 * LD;
#pragma unroll
            for (int n = 0; n < 8; n++) {
                const int pc = n * 8 + 2 * t;
                *(unsigned*)&Phs[pr0 + pc] = h2hi(S[n][0], S[n][1]);
                *(unsigned*)&Pls[pr0 + pc] = h2lo(S[n][0], S[n][1]);
                *(unsigned*)&Phs[pr1 + pc] = h2hi(S[n][2], S[n][3]);
                *(unsigned*)&Pls[pr1 + pc] = h2lo(S[n][2], S[n][3]);
            }
            __syncwarp();
#pragma unroll
            for (int s = 0; s < 4; s++) {
                unsigned pah[4], pal[4];
                ldmx4(pah, &Phs[(w * 16 + arow) * LD + s * 16 + acol8]);
                ldmx4(pal, &Pls[(w * 16 + arow) * LD + s * 16 + acol8]);
                const __half* vrow_h = &Vhs[(s * 16 + rsel) * LD];
#pragma unroll
                for (int nh = 0; nh < 2; nh++) {
                    unsigned vh[4][2];
#pragma unroll
                    for (int j = 0; j < 4; j++)
                        ldmx2t(vh[j][0], vh[j][1], vrow_h + (nh * 4 + j) * 8);
#pragma unroll
                    for (int j = 0; j < 4; j++)
                        mma_f16(O[nh * 4 + j], pah, vh[j][0], vh[j][1]);
#pragma unroll
                    for (int j = 0; j < 4; j++)
                        mma_f16(O[nh * 4 + j], pal, vh[j][0], vh[j][1]);
                }
            }
        }
        __syncthreads();                       // done reading buffer (kb&1)
        if (kb + 2 < nkb) ISSUE_KV(kb & 1, (kb + 2) * 64);
    }
#undef ISSUE_KV

    // epilogue: write y as fp16 hi/lo planes
    const int b_ = bh_ / HH, h = bh_ % HH;
    const float inv0 = 1.f / l0s, inv1 = 1.f / l1s;
    unsigned* yh = (unsigned*)g_yh;
    unsigned* yl = (unsigned*)g_yl;
#pragma unroll
    for (int n = 0; n < 8; n++) {
        int col = h * 64 + n * 8 + 2 * t;
        int r0 = qrow0 + g;
        size_t i0 = (((size_t)b_ * TT + r0) * CC + col) >> 1;
        size_t i1 = (((size_t)b_ * TT + r0 + 8) * CC + col) >> 1;
        float a0 = O[n][0] * inv0, a1 = O[n][1] * inv0;
        float a2 = O[n][2] * inv1, a3 = O[n][3] * inv1;
        yh[i0] = h2hi(a0, a1); yl[i0] = h2lo(a0, a1);
        yh[i1] = h2hi(a2, a3); yl[i1] = h2lo(a2, a3);
    }
}

// ---------------------------------------------------------------------------
// Launch: convert x/W -> qkv GEMM -> attention -> proj GEMM
// ---------------------------------------------------------------------------
static const int kGemmSmem = 2 * (2 * 64 * 72 + 128 * 72) * 2;     // 73728 B
static const int kAttnSmem = (2 * 2 * 64 * 72 + 2 * 128 * 72) * 2; // 73728 B

extern "C" void kernel_launch(void* const* d_in, const int* in_sizes, int n_in,
                              void* d_out, int out_size) {
    const float* x      = (const float*)d_in[0];
    const float* W_attn = (const float*)d_in[1];
    const float* b_attn = (const float*)d_in[2];
    const float* W_proj = (const float*)d_in[3];
    const float* b_proj = (const float*)d_in[4];
    float* out = (float*)d_out;

    cudaFuncSetAttribute(gemm_cp<true>,
                         cudaFuncAttributeMaxDynamicSharedMemorySize, kGemmSmem);
    cudaFuncSetAttribute(gemm_cp<false>,
                         cudaFuncAttributeMaxDynamicSharedMemorySize, kGemmSmem);
    cudaFuncSetAttribute(attn_tc,
                         cudaFuncAttributeMaxDynamicSharedMemorySize, kAttnSmem);

    __half *xh, *xl, *wah, *wph, *yh, *yl;
    cudaGetSymbolAddress((void**)&xh, g_xh);   cudaGetSymbolAddress((void**)&xl, g_xl);
    cudaGetSymbolAddress((void**)&wah, g_wah);
    cudaGetSymbolAddress((void**)&wph, g_wph);
    cudaGetSymbolAddress((void**)&yh, g_yh);   cudaGetSymbolAddress((void**)&yl, g_yl);

    // 0) convert inputs to fp16 planes (x: hi+lo, weights: hi only)
    cvt_hl<<<(MM * CC / 4) / 256, 256>>>(
        (const float4*)x, (uint2*)xh, (uint2*)xl, MM * CC / 4);
    cvt_h<<<(NQKV * CC / 4) / 256, 256>>>(
        (const float4*)W_attn, (uint2*)wah, NQKV * CC / 4);
    cvt_h<<<(CC * CC / 4) / 256, 256>>>(
        (const float4*)W_proj, (uint2*)wph, CC * CC / 4);

    // 1) qkv projection (q -> fp32, k/v -> fp16 hi planes)
    gemm_cp<true><<<dim3(NQKV / 128, MM / 64), 256, kGemmSmem>>>(
        xh, xl, wah, b_attn, nullptr, CC, NQKV);

    // 2) flash attention (cp.async K/V, writes y as fp16 hi/lo)
    attn_tc<<<dim3(TT / 128, BB * HH), 256, kAttnSmem>>>();

    // 3) output projection
    gemm_cp<false><<<dim3(CC / 128, MM / 64), 256, kGemmSmem>>>(
        yh, yl, wph, b_proj, out, CC, CC);
}

// round 16
// speedup vs baseline: 1.5136x; 1.0145x over previous
#include <cuda_runtime.h>
#include <cuda_fp16.h>
#include <math.h>

// Problem constants
#define BB 2
#define TT 2048
#define CC 1024
#define HH 16
#define HD 64
#define MM (BB*TT)        // 4096
#define NQKV (3*CC)       // 3072

// Scratch (device globals — allocation-free)
__device__ float g_q[(size_t)BB*HH*TT*HD];
__device__ __half g_kh[(size_t)BB*HH*TT*HD];
__device__ __half g_vh[(size_t)BB*HH*TT*HD];
__device__ __half g_xh[(size_t)MM*CC],   g_xl[(size_t)MM*CC];
__device__ __half g_wah[(size_t)NQKV*CC];
__device__ __half g_wph[(size_t)CC*CC];
__device__ __half g_yh[(size_t)MM*CC],   g_yl[(size_t)MM*CC];

// ---------------------------------------------------------------------------
// Helpers (fp16 hi/lo packing)
// ---------------------------------------------------------------------------
__device__ __forceinline__ unsigned h2hi(float x, float y) {
    __half2 p = __floats2half2_rn(x, y);
    return *(unsigned*)&p;
}
__device__ __forceinline__ unsigned h2lo(float x, float y) {
    float hx = __half2float(__float2half_rn(x));
    float hy = __half2float(__float2half_rn(y));
    return h2hi(x - hx, y - hy);
}
__device__ __forceinline__ void split4h(float4 v, uint2& h, uint2& l) {
    h.x = h2hi(v.x, v.y); h.y = h2hi(v.z, v.w);
    l.x = h2lo(v.x, v.y); l.y = h2lo(v.z, v.w);
}
__device__ __forceinline__ void hi4(float4 v, uint2& h) {
    h.x = h2hi(v.x, v.y); h.y = h2hi(v.z, v.w);
}
__device__ __forceinline__ unsigned smem_u32(const void* p) {
    return (unsigned)__cvta_generic_to_shared(p);
}
__device__ __forceinline__ void mma_f16(float d[4], const unsigned a[4],
                                        unsigned b0, unsigned b1) {
    asm volatile(
        "mma.sync.aligned.m16n8k16.row.col.f32.f16.f16.f32 "
        "{%0,%1,%2,%3}, {%4,%5,%6,%7}, {%8,%9}, {%0,%1,%2,%3};"
        : "+f"(d[0]), "+f"(d[1]), "+f"(d[2]), "+f"(d[3])
        : "r"(a[0]), "r"(a[1]), "r"(a[2]), "r"(a[3]), "r"(b0), "r"(b1));
}
__device__ __forceinline__ void ldmx4(unsigned r[4], const void* p) {
    unsigned addr = smem_u32(p);
    asm volatile("ldmatrix.sync.aligned.m8n8.x4.shared.b16 {%0,%1,%2,%3}, [%4];"
                 : "=r"(r[0]), "=r"(r[1]), "=r"(r[2]), "=r"(r[3]) : "r"(addr));
}
__device__ __forceinline__ void ldmx2t(unsigned& r0, unsigned& r1, const void* p) {
    unsigned addr = smem_u32(p);
    asm volatile("ldmatrix.sync.aligned.m8n8.x2.trans.shared.b16 {%0,%1}, [%2];"
                 : "=r"(r0), "=r"(r1) : "r"(addr));
}
__device__ __forceinline__ void cp_async16(unsigned dst, const void* src) {
    asm volatile("cp.async.cg.shared.global [%0], [%1], 16;"
                 :: "r"(dst), "l"(src) : "memory");
}
__device__ __forceinline__ void cp_commit() {
    asm volatile("cp.async.commit_group;" ::: "memory");
}

// ---------------------------------------------------------------------------
// Converts: fp32 -> fp16 planes
// ---------------------------------------------------------------------------
__global__ void cvt_hl(const float4* __restrict__ src, uint2* __restrict__ dh,
                       uint2* __restrict__ dl, int n4) {
    int i = blockIdx.x * blockDim.x + threadIdx.x;
    if (i < n4) {
        uint2 h, l;
        split4h(src[i], h, l);
        dh[i] = h;
        dl[i] = l;
    }
}
__global__ void cvt_h(const float4* __restrict__ src, uint2* __restrict__ dh, int n4) {
    int i = blockIdx.x * blockDim.x + threadIdx.x;
    if (i < n4) {
        uint2 h;
        hi4(src[i], h);
        dh[i] = h;
    }
}

// ---------------------------------------------------------------------------
// Pipelined fp16 x2 GEMM: out[m,n] = sum_k A[m,k]*W[n,k] + bias[n]
// A = Ah+Al (22-bit), W = Wh (11-bit). 64x128 tile, BK=64, THREE stages,
// ONE __syncthreads per iteration (prefetch it+2 issued before compute).
// 256 threads = 8 warps (2x4), 32x32/warp. smem 110592B/CTA -> 2 CTAs/SM.
// ---------------------------------------------------------------------------
template<bool QKV_SCATTER>
__global__ __launch_bounds__(256, 2)
void gemm_cp(const __half* __restrict__ Agh, const __half* __restrict__ Agl,
             const __half* __restrict__ Wgh,
             const float* __restrict__ bias, float* __restrict__ Cout,
             int K, int N) {
    constexpr int BK = 64, LD = 72;
    constexpr int APLANE = 64 * LD;
    constexpr int WPLANE = 128 * LD;
    constexpr int STAGE = 2 * APLANE + WPLANE;   // Ah, Al, Wh (18432 units)
    extern __shared__ __half sm[];               // 3 * STAGE

    const int tid = threadIdx.x;
    const int lane = tid & 31, w = tid >> 5;
    const int g = lane >> 2, t = lane & 3;
    const int m0 = blockIdx.y * 64, n0 = blockIdx.x * 128;
    const int wm = (w >> 2) * 32, wn = (w & 3) * 32;

    const int arow = lane & 15, acol8 = (lane >> 4) << 3;
    const int brow = (lane & 7) + ((lane >> 4) << 3), bcol8 = lane & 8;

#define ISSUE_STAGE(sidx, kt)                                                  \
    do {                                                                       \
        __half* sb = sm + (sidx) * STAGE;                                      \
        _Pragma("unroll")                                                      \
        for (int rep = 0; rep < 2; rep++) {                                    \
            int c = tid + rep * 256;                                           \
            int row = c >> 3, c8 = c & 7;                                      \
            cp_async16(smem_u32(sb + row * LD + c8 * 8),                       \
                       Agh + (size_t)(m0 + row) * K + (kt) + c8 * 8);          \
            cp_async16(smem_u32(sb + APLANE + row * LD + c8 * 8),              \
                       Agl + (size_t)(m0 + row) * K + (kt) + c8 * 8);          \
        }                                                                      \
        _Pragma("unroll")                                                      \
        for (int rep = 0; rep < 4; rep++) {                                    \
            int c = tid + rep * 256;                                           \
            int row = c >> 3, c8 = c & 7;                                      \
            cp_async16(smem_u32(sb + 2 * APLANE + row * LD + c8 * 8),          \
                       Wgh + (size_t)(n0 + row) * K + (kt) + c8 * 8);          \
        }                                                                      \
        cp_commit();                                                           \
    } while (0)

    float acc[2][4][4] = {};

    const int niter = K / BK;                 // 16
    ISSUE_STAGE(0, 0);
    ISSUE_STAGE(1, BK);

    for (int it = 0; it < niter; it++) {
        if (it + 1 < niter)
            asm volatile("cp.async.wait_group 1;" ::: "memory");
        else
            asm volatile("cp.async.wait_group 0;" ::: "memory");
        __syncthreads();
        // safe: compute of it-1 finished before this barrier, so its buffer
        // ((it+2)%3) is free to refill
        if (it + 2 < niter) ISSUE_STAGE((it + 2) % 3, (it + 2) * BK);

        const __half* Ah = sm + (it % 3) * STAGE;
        const __half* Al = Ah + APLANE;
        const __half* Wh = Al + APLANE;

#pragma unroll
        for (int s = 0; s < 4; s++) {
            const int kc0 = s * 16;
            unsigned ah[2][4], al[2][4];
            ldmx4(ah[0], &Ah[(wm + arow) * LD + kc0 + acol8]);
            ldmx4(ah[1], &Ah[(wm + 16 + arow) * LD + kc0 + acol8]);
            ldmx4(al[0], &Al[(wm + arow) * LD + kc0 + acol8]);
            ldmx4(al[1], &Al[(wm + 16 + arow) * LD + kc0 + acol8]);
            unsigned bh[4][2];
            {
                unsigned t0[4], t1[4];
                ldmx4(t0, &Wh[(wn + brow) * LD + kc0 + bcol8]);
                ldmx4(t1, &Wh[(wn + 16 + brow) * LD + kc0 + bcol8]);
                bh[0][0] = t0[0]; bh[0][1] = t0[1]; bh[1][0] = t0[2]; bh[1][1] = t0[3];
                bh[2][0] = t1[0]; bh[2][1] = t1[1]; bh[3][0] = t1[2]; bh[3][1] = t1[3];
            }
#pragma unroll
            for (int mi = 0; mi < 2; mi++)
#pragma unroll
                for (int ni = 0; ni < 4; ni++)
                    mma_f16(acc[mi][ni], ah[mi], bh[ni][0], bh[ni][1]);
#pragma unroll
            for (int mi = 0; mi < 2; mi++)
#pragma unroll
                for (int ni = 0; ni < 4; ni++)
                    mma_f16(acc[mi][ni], al[mi], bh[ni][0], bh[ni][1]);
        }
    }
#undef ISSUE_STAGE

    // epilogue
#pragma unroll
    for (int mi = 0; mi < 2; mi++)
#pragma unroll
        for (int ni = 0; ni < 4; ni++) {
            const int col = n0 + wn + ni * 8 + 2 * t;   // even
            const float b0f = __ldg(&bias[col]), b1f = __ldg(&bias[col + 1]);
            float v0 = acc[mi][ni][0] + b0f, v1 = acc[mi][ni][1] + b1f;
            float v2 = acc[mi][ni][2] + b0f, v3 = acc[mi][ni][3] + b1f;
            const int row0 = m0 + wm + mi * 16 + g, row1 = row0 + 8;
            if (QKV_SCATTER) {
                const int which = col >> 10;
                const int c = col & (CC - 1);
                const int h = c >> 6, d = c & 63;
#pragma unroll
                for (int rr = 0; rr < 2; rr++) {
                    int row = rr ? row1 : row0;
                    float a0 = rr ? v2 : v0, a1 = rr ? v3 : v1;
                    int b_ = row >> 11, tt = row & (TT - 1);
                    size_t base_i = ((size_t)(b_ * HH + h) * TT + tt) * HD + d;
                    if (which == 0) {
                        g_q[base_i] = a0;
                        g_q[base_i + 1] = a1;
                    } else {
                        size_t pi = base_i >> 1;
                        if (which == 1) ((unsigned*)g_kh)[pi] = h2hi(a0, a1);
                        else            ((unsigned*)g_vh)[pi] = h2hi(a0, a1);
                    }
                }
            } else {
                Cout[(size_t)row0 * N + col] = v0;
                Cout[(size_t)row0 * N + col + 1] = v1;
                Cout[(size_t)row1 * N + col] = v2;
                Cout[(size_t)row1 * N + col + 1] = v3;
            }
        }
}

// ---------------------------------------------------------------------------
// Tensor-core flash attention (fp16 x2), 128-row Q tiles, 256 threads,
// 2 CTAs/SM. K/V via THREE-stage cp.async, one __syncthreads per k-tile.
// ---------------------------------------------------------------------------
__global__ __launch_bounds__(256, 2)
void attn_tc() {
    constexpr int LD = 72;
    constexpr int PL = 64 * LD;                // plane units
    constexpr int KVSTAGE = 2 * PL;            // Kh, Vh (9216 units)
    extern __shared__ __half smb[];            // 3*KVSTAGE + 2*128*LD
    __half* Phs = smb + 3 * KVSTAGE;           // [128][72]
    __half* Pls = Phs + 128 * LD;

    const int tid = threadIdx.x;
    const int lane = tid & 31, w = tid >> 5;
    const int g = lane >> 2, t = lane & 3;
    const int qi = (int)gridDim.x - 1 - (int)blockIdx.x;  // big tiles first
    const int bh_ = blockIdx.y;

    const float* Qg = g_q + (size_t)bh_ * TT * HD;
    const __half* Kh_g = g_kh + (size_t)bh_ * TT * HD;
    const __half* Vh_g = g_vh + (size_t)bh_ * TT * HD;

    const int qrow0 = qi * 128 + w * 16;

    const int arow = lane & 15, acol8 = (lane >> 4) << 3;
    const int brow = (lane & 7) + ((lane >> 4) << 3), bcol8 = lane & 8;
    const int rsel = lane & 15;

#define ISSUE_KV(sidx, k0v)                                                    \
    do {                                                                       \
        __half* sb = smb + (sidx) * KVSTAGE;                                   \
        _Pragma("unroll")                                                      \
        for (int rep = 0; rep < 2; rep++) {                                    \
            int c = tid + rep * 256;                                           \
            int row = c >> 3, c8 = c & 7;                                      \
            size_t goff = (size_t)((k0v) + row) * HD + c8 * 8;                 \
            unsigned so = row * LD + c8 * 8;                                   \
            cp_async16(smem_u32(sb + so), Kh_g + goff);                        \
            cp_async16(smem_u32(sb + PL + so), Vh_g + goff);                   \
        }                                                                      \
        cp_commit();                                                           \
    } while (0)

    unsigned qh[4][4], ql[4][4];
#pragma unroll
    for (int s = 0; s < 4; s++) {
        const int c0 = s * 16 + 2 * t;
        float2 x00 = *(const float2*)&Qg[(size_t)(qrow0 + g) * 64 + c0];
        float2 x01 = *(const float2*)&Qg[(size_t)(qrow0 + g) * 64 + c0 + 8];
        float2 x10 = *(const float2*)&Qg[(size_t)(qrow0 + g + 8) * 64 + c0];
        float2 x11 = *(const float2*)&Qg[(size_t)(qrow0 + g + 8) * 64 + c0 + 8];
        x00.x *= 0.125f; x00.y *= 0.125f; x01.x *= 0.125f; x01.y *= 0.125f;
        x10.x *= 0.125f; x10.y *= 0.125f; x11.x *= 0.125f; x11.y *= 0.125f;
        qh[s][0] = h2hi(x00.x, x00.y); ql[s][0] = h2lo(x00.x, x00.y);
        qh[s][1] = h2hi(x10.x, x10.y); ql[s][1] = h2lo(x10.x, x10.y);
        qh[s][2] = h2hi(x01.x, x01.y); ql[s][2] = h2lo(x01.x, x01.y);
        qh[s][3] = h2hi(x11.x, x11.y); ql[s][3] = h2lo(x11.x, x11.y);
    }

    float m0s = -1e30f, m1s = -1e30f, l0s = 0.f, l1s = 0.f;
    float O[8][4] = {};

    const int nkb = 2 * qi + 2;
    ISSUE_KV(0, 0);
    ISSUE_KV(1, 64);

    for (int kb = 0; kb < nkb; kb++) {
        const int k0 = kb * 64;
        if (kb + 1 < nkb)
            asm volatile("cp.async.wait_group 1;" ::: "memory");
        else
            asm volatile("cp.async.wait_group 0;" ::: "memory");
        __syncthreads();
        if (kb + 2 < nkb) ISSUE_KV((kb + 2) % 3, (kb + 2) * 64);

        const __half* Khs = smb + (kb % 3) * KVSTAGE;
        const __half* Vhs = Khs + PL;

        if (k0 <= qrow0 + 15) {
            float S[8][4] = {};
#pragma unroll
            for (int s = 0; s < 4; s++) {
                const int kc0 = s * 16;
#pragma unroll
                for (int nh = 0; nh < 2; nh++) {
                    unsigned bh4[2][4];
                    const int kr = nh * 32 + brow;
                    ldmx4(bh4[0], &Khs[kr * LD + kc0 + bcol8]);
                    ldmx4(bh4[1], &Khs[(kr + 16) * LD + kc0 + bcol8]);
#pragma unroll
                    for (int j = 0; j < 4; j++)
                        mma_f16(S[nh * 4 + j], qh[s],
                                bh4[j >> 1][(j & 1) * 2], bh4[j >> 1][(j & 1) * 2 + 1]);
#pragma unroll
                    for (int j = 0; j < 4; j++)
                        mma_f16(S[nh * 4 + j], ql[s],
                                bh4[j >> 1][(j & 1) * 2], bh4[j >> 1][(j & 1) * 2 + 1]);
                }
            }
            if (k0 + 63 > qrow0) {
                int r0 = qrow0 + g, r1 = r0 + 8;
#pragma unroll
                for (int n = 0; n < 8; n++) {
                    int cb = k0 + n * 8 + 2 * t;
                    if (cb > r0)     S[n][0] = -1e30f;
                    if (cb + 1 > r0) S[n][1] = -1e30f;
                    if (cb > r1)     S[n][2] = -1e30f;
                    if (cb + 1 > r1) S[n][3] = -1e30f;
                }
            }
            float mx0 = -1e30f, mx1 = -1e30f;
#pragma unroll
            for (int n = 0; n < 8; n++) {
                mx0 = fmaxf(mx0, fmaxf(S[n][0], S[n][1]));
                mx1 = fmaxf(mx1, fmaxf(S[n][2], S[n][3]));
            }
            mx0 = fmaxf(mx0, __shfl_xor_sync(0xffffffffu, mx0, 1));
            mx0 = fmaxf(mx0, __shfl_xor_sync(0xffffffffu, mx0, 2));
            mx1 = fmaxf(mx1, __shfl_xor_sync(0xffffffffu, mx1, 1));
            mx1 = fmaxf(mx1, __shfl_xor_sync(0xffffffffu, mx1, 2));
            float mn0 = fmaxf(m0s, mx0), mn1 = fmaxf(m1s, mx1);
            float cr0 = __expf(m0s - mn0), cr1 = __expf(m1s - mn1);
            m0s = mn0; m1s = mn1;
            float rs0 = 0.f, rs1 = 0.f;
#pragma unroll
            for (int n = 0; n < 8; n++) {
                S[n][0] = __expf(S[n][0] - mn0);
                S[n][1] = __expf(S[n][1] - mn0);
                S[n][2] = __expf(S[n][2] - mn1);
                S[n][3] = __expf(S[n][3] - mn1);
                rs0 += S[n][0] + S[n][1];
                rs1 += S[n][2] + S[n][3];
            }
            rs0 += __shfl_xor_sync(0xffffffffu, rs0, 1);
            rs0 += __shfl_xor_sync(0xffffffffu, rs0, 2);
            rs1 += __shfl_xor_sync(0xffffffffu, rs1, 1);
            rs1 += __shfl_xor_sync(0xffffffffu, rs1, 2);
            l0s = l0s * cr0 + rs0;
            l1s = l1s * cr1 + rs1;
#pragma unroll
            for (int n = 0; n < 8; n++) {
                O[n][0] *= cr0; O[n][1] *= cr0;
                O[n][2] *= cr1; O[n][3] *= cr1;
            }
            const int pr0 = (w * 16 + g) * LD, pr1 = pr0 + 8 * LD;
#pragma unroll
            for (int n = 0; n < 8; n++) {
                const int pc = n * 8 + 2 * t;
                *(unsigned*)&Phs[pr0 + pc] = h2hi(S[n][0], S[n][1]);
                *(unsigned*)&Pls[pr0 + pc] = h2lo(S[n][0], S[n][1]);
                *(unsigned*)&Phs[pr1 + pc] = h2hi(S[n][2], S[n][3]);
                *(unsigned*)&Pls[pr1 + pc] = h2lo(S[n][2], S[n][3]);
            }
            __syncwarp();
#pragma unroll
            for (int s = 0; s < 4; s++) {
                unsigned pah[4], pal[4];
                ldmx4(pah, &Phs[(w * 16 + arow) * LD + s * 16 + acol8]);
                ldmx4(pal, &Pls[(w * 16 + arow) * LD + s * 16 + acol8]);
                const __half* vrow_h = &Vhs[(s * 16 + rsel) * LD];
#pragma unroll
                for (int nh = 0; nh < 2; nh++) {
                    unsigned vh[4][2];
#pragma unroll
                    for (int j = 0; j < 4; j++)
                        ldmx2t(vh[j][0], vh[j][1], vrow_h + (nh * 4 + j) * 8);
#pragma unroll
                    for (int j = 0; j < 4; j++)
                        mma_f16(O[nh * 4 + j], pah, vh[j][0], vh[j][1]);
#pragma unroll
                    for (int j = 0; j < 4; j++)
                        mma_f16(O[nh * 4 + j], pal, vh[j][0], vh[j][1]);
                }
            }
        }
    }
#undef ISSUE_KV

    // epilogue: write y as fp16 hi/lo planes
    const int b_ = bh_ / HH, h = bh_ % HH;
    const float inv0 = 1.f / l0s, inv1 = 1.f / l1s;
    unsigned* yh = (unsigned*)g_yh;
    unsigned* yl = (unsigned*)g_yl;
#pragma unroll
    for (int n = 0; n < 8; n++) {
        int col = h * 64 + n * 8 + 2 * t;
        int r0 = qrow0 + g;
        size_t i0 = (((size_t)b_ * TT + r0) * CC + col) >> 1;
        size_t i1 = (((size_t)b_ * TT + r0 + 8) * CC + col) >> 1;
        float a0 = O[n][0] * inv0, a1 = O[n][1] * inv0;
        float a2 = O[n][2] * inv1, a3 = O[n][3] * inv1;
        yh[i0] = h2hi(a0, a1); yl[i0] = h2lo(a0, a1);
        yh[i1] = h2hi(a2, a3); yl[i1] = h2lo(a2, a3);
    }
}

// ---------------------------------------------------------------------------
// Launch: convert x/W -> qkv GEMM -> attention -> proj GEMM
// ---------------------------------------------------------------------------
static const int kGemmSmem = 3 * (2 * 64 * 72 + 128 * 72) * 2;     // 110592 B
static const int kAttnSmem = (3 * 2 * 64 * 72 + 2 * 128 * 72) * 2; // 92160 B

extern "C" void kernel_launch(void* const* d_in, const int* in_sizes, int n_in,
                              void* d_out, int out_size) {
    const float* x      = (const float*)d_in[0];
    const float* W_attn = (const float*)d_in[1];
    const float* b_attn = (const float*)d_in[2];
    const float* W_proj = (const float*)d_in[3];
    const float* b_proj = (const float*)d_in[4];
    float* out = (float*)d_out;

    cudaFuncSetAttribute(gemm_cp<true>,
                         cudaFuncAttributeMaxDynamicSharedMemorySize, kGemmSmem);
    cudaFuncSetAttribute(gemm_cp<false>,
                         cudaFuncAttributeMaxDynamicSharedMemorySize, kGemmSmem);
    cudaFuncSetAttribute(attn_tc,
                         cudaFuncAttributeMaxDynamicSharedMemorySize, kAttnSmem);

    __half *xh, *xl, *wah, *wph, *yh, *yl;
    cudaGetSymbolAddress((void**)&xh, g_xh);   cudaGetSymbolAddress((void**)&xl, g_xl);
    cudaGetSymbolAddress((void**)&wah, g_wah);
    cudaGetSymbolAddress((void**)&wph, g_wph);
    cudaGetSymbolAddress((void**)&yh, g_yh);   cudaGetSymbolAddress((void**)&yl, g_yl);

    // 0) convert inputs to fp16 planes (x: hi+lo, weights: hi only)
    cvt_hl<<<(MM * CC / 4) / 256, 256>>>(
        (const float4*)x, (uint2*)xh, (uint2*)xl, MM * CC / 4);
    cvt_h<<<(NQKV * CC / 4) / 256, 256>>>(
        (const float4*)W_attn, (uint2*)wah, NQKV * CC / 4);
    cvt_h<<<(CC * CC / 4) / 256, 256>>>(
        (const float4*)W_proj, (uint2*)wph, CC * CC / 4);

    // 1) qkv projection (q -> fp32, k/v -> fp16 hi planes)
    gemm_cp<true><<<dim3(NQKV / 128, MM / 64), 256, kGemmSmem>>>(
        xh, xl, wah, b_attn, nullptr, CC, NQKV);

    // 2) flash attention (3-stage cp.async K/V, writes y as fp16 hi/lo)
    attn_tc<<<dim3(TT / 128, BB * HH), 256, kAttnSmem>>>();

    // 3) output projection
    gemm_cp<false><<<dim3(CC / 128, MM / 64), 256, kGemmSmem>>>(
        yh, yl, wph, b_proj, out, CC, CC);
}